// round 3
// baseline (speedup 1.0000x reference)
#include <cuda_runtime.h>
#include <cuda_bf16.h>
#include <cstddef>

// Problem constants
// B=8, N=196, C=512, NC=10, H=8, HD=64, SCALE=0.125
// x: (8,196,512), anchors: (10,196,512), weights: (8,8,10)
// Output: concat[ out (8*196*512 = 802816), left_attn (8*10*8*196*196 = 24586240) ]

#define Bb 8
#define Nn 196
#define Cc 512
#define NCc 10
#define Hh 8
#define HDd 64
#define SCALE 0.125f
#define NBATCH (Bb*NCc*Hh)      // 640
#define ATT_SZ (Nn*Nn)          // 38416
#define RV_SZ (Nn*HDd)          // 12544

// Scratch (device globals; no allocation)
__device__ float g_xq [Bb*Nn*Cc];       // x @ Wqk
__device__ float g_xq2[Bb*Nn*Cc];       // x @ Wqk2
__device__ float g_xv [Bb*Nn*Cc];       // x @ Wv
__device__ float g_aq [NCc*Nn*Cc];      // anchors @ Wqk
__device__ float g_aq2[NCc*Nn*Cc];      // anchors @ Wqk2
__device__ float g_right[NBATCH*ATT_SZ];// right_attn
__device__ float g_rv[NBATCH*RV_SZ];    // right_attn @ v
__device__ float g_ofull[Bb*Nn*Cc];     // pre-proj output (flattened H,N,HD order)

// ----------------------------------------------------------------------------
// Generic GEMM: C[M,512] = A[M,512] @ B[512,512] (+ bias). Tile 64x64, BK=32.
// ----------------------------------------------------------------------------
__global__ void gemm512_kernel(const float* __restrict__ A,
                               const float* __restrict__ Bm,
                               const float* __restrict__ bias,
                               float* __restrict__ Cm, int M) {
    __shared__ float As[64][33];
    __shared__ float Bs[32][65];
    int tid = threadIdx.x;
    int tx = tid & 15, ty = tid >> 4;
    int row0 = blockIdx.x * 64, col0 = blockIdx.y * 64;
    float acc[4][4] = {};
    for (int k0 = 0; k0 < 512; k0 += 32) {
        #pragma unroll
        for (int idx = tid; idx < 64 * 32; idx += 256) {
            int r = idx >> 5, c = idx & 31;
            As[r][c] = (row0 + r < M) ? A[(size_t)(row0 + r) * 512 + k0 + c] : 0.f;
        }
        #pragma unroll
        for (int idx = tid; idx < 32 * 64; idx += 256) {
            int r = idx >> 6, c = idx & 63;
            Bs[r][c] = Bm[(size_t)(k0 + r) * 512 + col0 + c];
        }
        __syncthreads();
        #pragma unroll
        for (int kk = 0; kk < 32; kk++) {
            float a[4], bb[4];
            #pragma unroll
            for (int i = 0; i < 4; i++) a[i] = As[ty * 4 + i][kk];
            #pragma unroll
            for (int j = 0; j < 4; j++) bb[j] = Bs[kk][tx * 4 + j];
            #pragma unroll
            for (int i = 0; i < 4; i++)
                #pragma unroll
                for (int j = 0; j < 4; j++) acc[i][j] += a[i] * bb[j];
        }
        __syncthreads();
    }
    #pragma unroll
    for (int i = 0; i < 4; i++) {
        int r = row0 + ty * 4 + i;
        if (r < M) {
            #pragma unroll
            for (int j = 0; j < 4; j++) {
                int cj = col0 + tx * 4 + j;
                float v = acc[i][j];
                if (bias) v += bias[cj];
                Cm[(size_t)r * 512 + cj] = v;
            }
        }
    }
}

// ----------------------------------------------------------------------------
// Batched relu attention: out[batch,i,j] = relu(scale * dot(Arow_i, Brow_j))
// batch = (b*NC + c)*H + h.
// swap=0 (left):  rows from Px (b), cols from Pa (c); scale = -SCALE
// swap=1 (right): rows from Pa (c), cols from Px (b); scale = +SCALE
// ----------------------------------------------------------------------------
__global__ void attn_kernel(const float* __restrict__ Px,
                            const float* __restrict__ Pa,
                            float* __restrict__ out, float scale, int swap) {
    __shared__ float Ar[64][65];
    __shared__ float Br[64][65];
    int batch = blockIdx.y;
    int h = batch & 7;
    int c = (batch >> 3) % 10;
    int b = batch / 80;
    int i0 = (blockIdx.x >> 2) * 64;
    int j0 = (blockIdx.x & 3) * 64;
    const float* Abase;
    const float* Bbase;
    if (!swap) {
        Abase = Px + (size_t)(b * Nn) * 512 + h * 64;
        Bbase = Pa + (size_t)(c * Nn) * 512 + h * 64;
    } else {
        Abase = Pa + (size_t)(c * Nn) * 512 + h * 64;
        Bbase = Px + (size_t)(b * Nn) * 512 + h * 64;
    }
    int tid = threadIdx.x;
    #pragma unroll
    for (int idx = tid; idx < 64 * 64; idx += 256) {
        int r = idx >> 6, d = idx & 63;
        Ar[r][d] = (i0 + r < Nn) ? Abase[(size_t)(i0 + r) * 512 + d] : 0.f;
        Br[r][d] = (j0 + r < Nn) ? Bbase[(size_t)(j0 + r) * 512 + d] : 0.f;
    }
    __syncthreads();
    int tx = tid & 15, ty = tid >> 4;
    float acc[4][4] = {};
    #pragma unroll
    for (int k = 0; k < 64; k++) {
        float a[4], bb[4];
        #pragma unroll
        for (int i = 0; i < 4; i++) a[i] = Ar[ty * 4 + i][k];
        #pragma unroll
        for (int j = 0; j < 4; j++) bb[j] = Br[tx * 4 + j][k];
        #pragma unroll
        for (int i = 0; i < 4; i++)
            #pragma unroll
            for (int j = 0; j < 4; j++) acc[i][j] += a[i] * bb[j];
    }
    float* ob = out + (size_t)batch * ATT_SZ;
    #pragma unroll
    for (int i = 0; i < 4; i++) {
        int gi = i0 + ty * 4 + i;
        if (gi < Nn) {
            #pragma unroll
            for (int j = 0; j < 4; j++) {
                int gj = j0 + tx * 4 + j;
                if (gj < Nn)
                    ob[(size_t)gi * Nn + gj] = fmaxf(acc[i][j] * scale, 0.f);
            }
        }
    }
}

// ----------------------------------------------------------------------------
// RV[batch] = right[batch] (196x196) @ v[b,h] (196x64)
// ----------------------------------------------------------------------------
__global__ void rv_kernel() {
    __shared__ float Rt[64][65];
    __shared__ float Vt[64][65];
    int batch = blockIdx.y;
    int h = batch & 7;
    int b = batch / 80;
    int i0 = blockIdx.x * 64;
    int tid = threadIdx.x;
    int tx = tid & 15, ty = tid >> 4;
    float acc[4][4] = {};
    const float* Rb = g_right + (size_t)batch * ATT_SZ;
    for (int m0 = 0; m0 < Nn; m0 += 64) {
        #pragma unroll
        for (int idx = tid; idx < 64 * 64; idx += 256) {
            int r = idx >> 6, cc = idx & 63;
            Rt[r][cc] = (i0 + r < Nn && m0 + cc < Nn) ? Rb[(size_t)(i0 + r) * Nn + m0 + cc] : 0.f;
            Vt[r][cc] = (m0 + r < Nn) ? g_xv[(size_t)(b * Nn + m0 + r) * 512 + h * 64 + cc] : 0.f;
        }
        __syncthreads();
        #pragma unroll
        for (int k = 0; k < 64; k++) {
            float a[4], bb[4];
            #pragma unroll
            for (int i = 0; i < 4; i++) a[i] = Rt[ty * 4 + i][k];
            #pragma unroll
            for (int j = 0; j < 4; j++) bb[j] = Vt[k][tx * 4 + j];
            #pragma unroll
            for (int i = 0; i < 4; i++)
                #pragma unroll
                for (int j = 0; j < 4; j++) acc[i][j] += a[i] * bb[j];
        }
        __syncthreads();
    }
    float* rb = g_rv + (size_t)batch * RV_SZ;
    #pragma unroll
    for (int i = 0; i < 4; i++) {
        int gi = i0 + ty * 4 + i;
        if (gi < Nn) {
            #pragma unroll
            for (int j = 0; j < 4; j++)
                rb[(size_t)gi * 64 + tx * 4 + j] = acc[i][j];
        }
    }
}

// ----------------------------------------------------------------------------
// o[b,h] (196x64) = sum_c w[b,h,c] * left[b,c,h] @ RV[b,c,h]
// Written in the reference's flatten order: ofull[b, h*N*HD + i*HD + d]
// ----------------------------------------------------------------------------
__global__ void combine_kernel(const float* __restrict__ left,
                               const float* __restrict__ w) {
    __shared__ float Lt[64][65];
    __shared__ float Rt[64][65];
    int bh = blockIdx.y;
    int b = bh >> 3, h = bh & 7;
    int i0 = blockIdx.x * 64;
    int tid = threadIdx.x;
    int tx = tid & 15, ty = tid >> 4;
    float acc[4][4] = {};
    for (int c = 0; c < NCc; c++) {
        float wc = w[(b * Hh + h) * NCc + c];
        int batch = (b * NCc + c) * Hh + h;
        const float* Lb = left + (size_t)batch * ATT_SZ;
        const float* Rb = g_rv + (size_t)batch * RV_SZ;
        for (int j0 = 0; j0 < Nn; j0 += 64) {
            #pragma unroll
            for (int idx = tid; idx < 64 * 64; idx += 256) {
                int r = idx >> 6, cc = idx & 63;
                Lt[r][cc] = (i0 + r < Nn && j0 + cc < Nn)
                                ? Lb[(size_t)(i0 + r) * Nn + j0 + cc] * wc : 0.f;
                Rt[r][cc] = (j0 + r < Nn) ? Rb[(size_t)(j0 + r) * 64 + cc] : 0.f;
            }
            __syncthreads();
            #pragma unroll
            for (int k = 0; k < 64; k++) {
                float a[4], bb[4];
                #pragma unroll
                for (int i = 0; i < 4; i++) a[i] = Lt[ty * 4 + i][k];
                #pragma unroll
                for (int j = 0; j < 4; j++) bb[j] = Rt[k][tx * 4 + j];
                #pragma unroll
                for (int i = 0; i < 4; i++)
                    #pragma unroll
                    for (int j = 0; j < 4; j++) acc[i][j] += a[i] * bb[j];
            }
            __syncthreads();
        }
    }
    // ofull[b, h*N*HD + i*HD + d]  (N*C = 100352 floats per b)
    float* ob = g_ofull + (size_t)b * (Nn * Cc) + (size_t)h * (Nn * HDd);
    #pragma unroll
    for (int i = 0; i < 4; i++) {
        int gi = i0 + ty * 4 + i;
        if (gi < Nn) {
            #pragma unroll
            for (int j = 0; j < 4; j++)
                ob[(size_t)gi * HDd + tx * 4 + j] = acc[i][j];
        }
    }
}

extern "C" void kernel_launch(void* const* d_in, const int* in_sizes, int n_in,
                              void* d_out, int out_size) {
    const float* x       = (const float*)d_in[0];
    const float* anchors = (const float*)d_in[1];
    const float* weights = (const float*)d_in[2];
    const float* Wqk     = (const float*)d_in[3];
    const float* Wqk2    = (const float*)d_in[4];
    const float* Wv      = (const float*)d_in[5];
    const float* Wproj   = (const float*)d_in[6];
    const float* bproj   = (const float*)d_in[7];

    float* out  = (float*)d_out;                 // (B,N,C) = 802816 floats
    float* left = out + (size_t)Bb * Nn * Cc;    // left_attn = 24586240 floats

    float *xq, *xq2, *xv, *aq, *aq2, *right, *ofull;
    cudaGetSymbolAddress((void**)&xq,    g_xq);
    cudaGetSymbolAddress((void**)&xq2,   g_xq2);
    cudaGetSymbolAddress((void**)&xv,    g_xv);
    cudaGetSymbolAddress((void**)&aq,    g_aq);
    cudaGetSymbolAddress((void**)&aq2,   g_aq2);
    cudaGetSymbolAddress((void**)&right, g_right);
    cudaGetSymbolAddress((void**)&ofull, g_ofull);

    const int MX = Bb * Nn;    // 1568
    const int MA = NCc * Nn;   // 1960

    // Projections
    gemm512_kernel<<<dim3((MX + 63) / 64, 8), 256>>>(x, Wqk,  nullptr, xq,  MX);
    gemm512_kernel<<<dim3((MX + 63) / 64, 8), 256>>>(x, Wqk2, nullptr, xq2, MX);
    gemm512_kernel<<<dim3((MX + 63) / 64, 8), 256>>>(x, Wv,   nullptr, xv,  MX);
    gemm512_kernel<<<dim3((MA + 63) / 64, 8), 256>>>(anchors, Wqk,  nullptr, aq,  MA);
    gemm512_kernel<<<dim3((MA + 63) / 64, 8), 256>>>(anchors, Wqk2, nullptr, aq2, MA);

    // left_attn -> output buffer directly; right_attn -> scratch
    attn_kernel<<<dim3(16, NBATCH), 256>>>(xq,  aq,  left,  -SCALE, 0);
    attn_kernel<<<dim3(16, NBATCH), 256>>>(xq2, aq2, right,  SCALE, 1);

    // RV = right @ v (per batch)
    rv_kernel<<<dim3(4, NBATCH), 256>>>();

    // o = sum_c w_c * left_c @ RV_c   (into ofull, reference flatten order)
    combine_kernel<<<dim3(4, Bb * Hh), 256>>>(left, weights);

    // Final projection + bias
    gemm512_kernel<<<dim3((MX + 63) / 64, 8), 256>>>(ofull, Wproj, bproj, out, MX);
}

// round 8
// speedup vs baseline: 1.6671x; 1.6671x over previous
#include <cuda_runtime.h>
#include <cstddef>

// B=8, N=196, C=512, NC=10, H=8, HD=64, SCALE=0.125
#define Bb 8
#define Nn 196
#define Cc 512
#define NCc 10
#define Hh 8
#define HDd 64
#define SCALE 0.125f
#define NBATCH (Bb*NCc*Hh)      // 640
#define ATT_SZ (Nn*Nn)          // 38416
#define RV_SZ (Nn*HDd)          // 12544

// Scratch (device globals; no allocation)
__device__ float g_xq   [Bb*Nn*Cc];
__device__ float g_xq2  [Bb*Nn*Cc];
__device__ float g_xv   [Bb*Nn*Cc];
__device__ float g_aq   [NCc*Nn*Cc];
__device__ float g_aq2  [NCc*Nn*Cc];
__device__ float g_rv   [NBATCH*RV_SZ];
__device__ float g_of0  [Bb*Nn*Cc];
__device__ float g_of1  [Bb*Nn*Cc];

#define F4(p) (*(const float4*)(p))
static __device__ __forceinline__ float4 f4zero() { return make_float4(0.f,0.f,0.f,0.f); }

// ----------------------------------------------------------------------------
// GEMM: O[M,512] = (A (+A2))[M,512] @ W[512,512] (+bias). blockIdx.z selects W/O.
// 64x64 tile, BK=32, 128 threads, 8x4 micro-tile, float4 smem loads.
// ----------------------------------------------------------------------------
__global__ __launch_bounds__(128) void gemm_multi(
    const float* __restrict__ A, const float* __restrict__ A2,
    const float* __restrict__ W0, const float* __restrict__ W1, const float* __restrict__ W2,
    float* __restrict__ O0, float* __restrict__ O1, float* __restrict__ O2,
    const float* __restrict__ bias, int M)
{
    __shared__ __align__(16) float Asm[32][68];   // [k][row]
    __shared__ __align__(16) float Bsm[32][68];   // [k][col]
    int z = blockIdx.z;
    const float* W = (z == 0) ? W0 : (z == 1 ? W1 : W2);
    float*       O = (z == 0) ? O0 : (z == 1 ? O1 : O2);

    int tid = threadIdx.x;
    int tx = tid & 15, ty = tid >> 4;       // col = tx*4, row = ty*8
    int row0 = blockIdx.x * 64, col0 = blockIdx.y * 64;

    float acc[8][4] = {};
    for (int k0 = 0; k0 < 512; k0 += 32) {
        #pragma unroll
        for (int u = 0; u < 4; u++) {
            int f = tid + u * 128;          // 512 quads
            int r = f >> 3, q = f & 7;
            float4 v = f4zero();
            if (row0 + r < M) {
                v = F4(A + (size_t)(row0 + r) * 512 + k0 + q * 4);
                if (A2) {
                    float4 v2 = F4(A2 + (size_t)(row0 + r) * 512 + k0 + q * 4);
                    v.x += v2.x; v.y += v2.y; v.z += v2.z; v.w += v2.w;
                }
            }
            Asm[q*4+0][r] = v.x; Asm[q*4+1][r] = v.y;
            Asm[q*4+2][r] = v.z; Asm[q*4+3][r] = v.w;
        }
        #pragma unroll
        for (int u = 0; u < 4; u++) {
            int f = tid + u * 128;
            int kk = f >> 4, q = f & 15;
            *(float4*)&Bsm[kk][q*4] = F4(W + (size_t)(k0 + kk) * 512 + col0 + q * 4);
        }
        __syncthreads();
        #pragma unroll
        for (int kk = 0; kk < 32; kk++) {
            float4 a0 = *(const float4*)&Asm[kk][ty*8];
            float4 a1 = *(const float4*)&Asm[kk][ty*8+4];
            float4 b  = *(const float4*)&Bsm[kk][tx*4];
            float av[8] = {a0.x,a0.y,a0.z,a0.w,a1.x,a1.y,a1.z,a1.w};
            float bv[4] = {b.x,b.y,b.z,b.w};
            #pragma unroll
            for (int i = 0; i < 8; i++)
                #pragma unroll
                for (int j = 0; j < 4; j++) acc[i][j] += av[i] * bv[j];
        }
        __syncthreads();
    }
    float4 bv4 = bias ? F4(bias + col0 + tx*4) : f4zero();
    #pragma unroll
    for (int i = 0; i < 8; i++) {
        int r = row0 + ty*8 + i;
        if (r < M) {
            *(float4*)(O + (size_t)r * 512 + col0 + tx*4) =
                make_float4(acc[i][0]+bv4.x, acc[i][1]+bv4.y,
                            acc[i][2]+bv4.z, acc[i][3]+bv4.w);
        }
    }
}

// ----------------------------------------------------------------------------
// left_attn[batch][i][j] = relu(-SCALE * dot(xq[b,i0+i,h], aq[c,j0+j,h]))
// ----------------------------------------------------------------------------
__global__ __launch_bounds__(128) void attn_left_kernel(
    const float* __restrict__ xq, const float* __restrict__ aq,
    float* __restrict__ out)
{
    __shared__ __align__(16) float Qs[64][68];  // [d][i]
    __shared__ __align__(16) float Ks[64][68];  // [d][j]
    int batch = blockIdx.y;
    int h = batch & 7, c = (batch >> 3) % 10, b = batch / 80;
    int i0 = (blockIdx.x >> 2) * 64, j0 = (blockIdx.x & 3) * 64;
    const float* Qb = xq + (size_t)b * Nn * Cc + h * HDd;
    const float* Kb = aq + (size_t)c * Nn * Cc + h * HDd;
    int tid = threadIdx.x, tx = tid & 15, ty = tid >> 4;

    #pragma unroll
    for (int u = 0; u < 8; u++) {
        int f = tid + u * 128;              // 1024 quads each buffer
        int r = f >> 4, q = f & 15;
        float4 v = (i0 + r < Nn) ? F4(Qb + (size_t)(i0 + r) * Cc + q * 4) : f4zero();
        Qs[q*4+0][r] = v.x; Qs[q*4+1][r] = v.y; Qs[q*4+2][r] = v.z; Qs[q*4+3][r] = v.w;
        float4 w = (j0 + r < Nn) ? F4(Kb + (size_t)(j0 + r) * Cc + q * 4) : f4zero();
        Ks[q*4+0][r] = w.x; Ks[q*4+1][r] = w.y; Ks[q*4+2][r] = w.z; Ks[q*4+3][r] = w.w;
    }
    __syncthreads();

    float acc[8][4] = {};
    #pragma unroll
    for (int k = 0; k < 64; k++) {
        float4 a0 = *(const float4*)&Qs[k][ty*8];
        float4 a1 = *(const float4*)&Qs[k][ty*8+4];
        float4 bq = *(const float4*)&Ks[k][tx*4];
        float av[8] = {a0.x,a0.y,a0.z,a0.w,a1.x,a1.y,a1.z,a1.w};
        float bvv[4] = {bq.x,bq.y,bq.z,bq.w};
        #pragma unroll
        for (int i = 0; i < 8; i++)
            #pragma unroll
            for (int j = 0; j < 4; j++) acc[i][j] += av[i] * bvv[j];
    }
    float* ob = out + (size_t)batch * ATT_SZ;
    int gj = j0 + tx * 4;
    if (gj < Nn) {
        #pragma unroll
        for (int i = 0; i < 8; i++) {
            int gi = i0 + ty*8 + i;
            if (gi < Nn) {
                *(float4*)(ob + (size_t)gi * Nn + gj) =
                    make_float4(fmaxf(acc[i][0]*(-SCALE),0.f),
                                fmaxf(acc[i][1]*(-SCALE),0.f),
                                fmaxf(acc[i][2]*(-SCALE),0.f),
                                fmaxf(acc[i][3]*(-SCALE),0.f));
            }
        }
    }
}

// ----------------------------------------------------------------------------
// Fused right-attn + RV: rv[batch][i][d] = sum_j relu(SCALE*k2_i·q2_j)*v[b,j,d]
// STATIC smem = 3 * 64*64 floats = 48KB exactly. Q2 tile and S tile alias.
// ----------------------------------------------------------------------------
__global__ __launch_bounds__(128) void right_rv_kernel(
    const float* __restrict__ xq2, const float* __restrict__ aq2,
    const float* __restrict__ xv, float* __restrict__ rv)
{
    __shared__ __align__(16) float sm[3 * 64 * 64];   // 49152 bytes
    float* K2s = sm;            // [d][i]  (transposed)
    float* QSs = sm + 4096;     // Q2 as [d][j]; after stage1, S as [j][i]
    float* Vs  = sm + 8192;     // [j][d]  (row-major)

    int batch = blockIdx.y;
    int h = batch & 7, c = (batch >> 3) % 10, b = batch / 80;
    int i0 = blockIdx.x * 64;
    const float* Kb = aq2 + (size_t)c * Nn * Cc + h * HDd;
    const float* Qb = xq2 + (size_t)b * Nn * Cc + h * HDd;
    const float* Vb = xv  + (size_t)b * Nn * Cc + h * HDd;
    int tid = threadIdx.x, tx = tid & 15, ty = tid >> 4;

    // K2 tile (transposed). Remapped fill: 2-way write conflicts max.
    #pragma unroll
    for (int u = 0; u < 8; u++) {
        int f = tid + u * 128;
        int q = (f & 1) | ((f >> 7) << 1);   // 0..15 (d quads)
        int r = (f >> 1) & 63;               // 0..63 (i)
        float4 v = (i0 + r < Nn) ? F4(Kb + (size_t)(i0 + r) * Cc + q * 4) : f4zero();
        K2s[(q*4+0)*64 + r] = v.x; K2s[(q*4+1)*64 + r] = v.y;
        K2s[(q*4+2)*64 + r] = v.z; K2s[(q*4+3)*64 + r] = v.w;
    }

    float acc[8][4] = {};
    for (int j0 = 0; j0 < 256; j0 += 64) {
        __syncthreads();   // prev stage2 done with QSs/Vs (no-op cost on iter 0)
        // Q2 tile (transposed into QSs) + V tile (row-major)
        #pragma unroll
        for (int u = 0; u < 8; u++) {
            int f = tid + u * 128;
            int q = (f & 1) | ((f >> 7) << 1);
            int r = (f >> 1) & 63;
            float4 v = (j0 + r < Nn) ? F4(Qb + (size_t)(j0 + r) * Cc + q * 4) : f4zero();
            QSs[(q*4+0)*64 + r] = v.x; QSs[(q*4+1)*64 + r] = v.y;
            QSs[(q*4+2)*64 + r] = v.z; QSs[(q*4+3)*64 + r] = v.w;
            int rv_ = f >> 4, qv = f & 15;
            float4 w = (j0 + rv_ < Nn) ? F4(Vb + (size_t)(j0 + rv_) * Cc + qv * 4) : f4zero();
            *(float4*)&Vs[rv_*64 + qv*4] = w;
        }
        __syncthreads();
        // Stage 1: s[i][j] = K2_i · Q2_j
        float s[8][4] = {};
        #pragma unroll
        for (int d = 0; d < 64; d++) {
            float4 a0 = *(const float4*)&K2s[d*64 + ty*8];
            float4 a1 = *(const float4*)&K2s[d*64 + ty*8+4];
            float4 bq = *(const float4*)&QSs[d*64 + tx*4];
            float av[8] = {a0.x,a0.y,a0.z,a0.w,a1.x,a1.y,a1.z,a1.w};
            float bvv[4] = {bq.x,bq.y,bq.z,bq.w};
            #pragma unroll
            for (int i = 0; i < 8; i++)
                #pragma unroll
                for (int j = 0; j < 4; j++) s[i][j] += av[i] * bvv[j];
        }
        __syncthreads();   // everyone done reading QSs as Q2
        // Write S = relu(SCALE*s) into QSs as [j][i]
        #pragma unroll
        for (int j = 0; j < 4; j++) {
            *(float4*)&QSs[(tx*4+j)*64 + ty*8] =
                make_float4(fmaxf(s[0][j]*SCALE,0.f), fmaxf(s[1][j]*SCALE,0.f),
                            fmaxf(s[2][j]*SCALE,0.f), fmaxf(s[3][j]*SCALE,0.f));
            *(float4*)&QSs[(tx*4+j)*64 + ty*8+4] =
                make_float4(fmaxf(s[4][j]*SCALE,0.f), fmaxf(s[5][j]*SCALE,0.f),
                            fmaxf(s[6][j]*SCALE,0.f), fmaxf(s[7][j]*SCALE,0.f));
        }
        __syncthreads();   // S visible
        // Stage 2: acc += S · V
        #pragma unroll
        for (int j = 0; j < 64; j++) {
            float4 a0 = *(const float4*)&QSs[j*64 + ty*8];
            float4 a1 = *(const float4*)&QSs[j*64 + ty*8+4];
            float4 bq = *(const float4*)&Vs[j*64 + tx*4];
            float av[8] = {a0.x,a0.y,a0.z,a0.w,a1.x,a1.y,a1.z,a1.w};
            float bvv[4] = {bq.x,bq.y,bq.z,bq.w};
            #pragma unroll
            for (int i = 0; i < 8; i++)
                #pragma unroll
                for (int jj = 0; jj < 4; jj++) acc[i][jj] += av[i] * bvv[jj];
        }
    }
    float* rb = rv + (size_t)batch * RV_SZ;
    #pragma unroll
    for (int i = 0; i < 8; i++) {
        int gi = i0 + ty*8 + i;
        if (gi < Nn)
            *(float4*)(rb + (size_t)gi * HDd + tx*4) =
                make_float4(acc[i][0], acc[i][1], acc[i][2], acc[i][3]);
    }
}

// ----------------------------------------------------------------------------
// combine: of_z[b,h,i,d] = sum_{c in z-group} w[b,h,c] * (L_c @ RV_c)[i,d]
// ----------------------------------------------------------------------------
__global__ __launch_bounds__(128) void combine_kernel(
    const float* __restrict__ left, const float* __restrict__ w,
    const float* __restrict__ rv, float* __restrict__ of0, float* __restrict__ of1)
{
    __shared__ __align__(16) float Ls[64][68];  // [m][i], pre-scaled by wc
    __shared__ __align__(16) float Rs[64][68];  // [m][d]
    int bh = blockIdx.y;
    int b = bh >> 3, h = bh & 7;
    int i0 = blockIdx.x * 64;
    int z = blockIdx.z;
    float* ofull = z ? of1 : of0;
    int tid = threadIdx.x, tx = tid & 15, ty = tid >> 4;

    float acc[8][4] = {};
    for (int cc = 0; cc < 5; cc++) {
        int c = z * 5 + cc;
        float wc = w[(b * Hh + h) * NCc + c];
        int batch = (b * NCc + c) * Hh + h;
        const float* Lb = left + (size_t)batch * ATT_SZ;
        const float* Rb = rv + (size_t)batch * RV_SZ;
        for (int m0 = 0; m0 < 256; m0 += 64) {
            #pragma unroll
            for (int u = 0; u < 8; u++) {
                int f = tid + u * 128;
                int r = f >> 4, q = f & 15;
                float4 v = (i0 + r < Nn && m0 + q*4 < Nn)
                         ? F4(Lb + (size_t)(i0 + r) * Nn + m0 + q*4) : f4zero();
                Ls[q*4+0][r] = v.x * wc; Ls[q*4+1][r] = v.y * wc;
                Ls[q*4+2][r] = v.z * wc; Ls[q*4+3][r] = v.w * wc;
                float4 rvv = (m0 + r < Nn)
                         ? F4(Rb + (size_t)(m0 + r) * HDd + q*4) : f4zero();
                *(float4*)&Rs[r][q*4] = rvv;
            }
            __syncthreads();
            #pragma unroll
            for (int m = 0; m < 64; m++) {
                float4 a0 = *(const float4*)&Ls[m][ty*8];
                float4 a1 = *(const float4*)&Ls[m][ty*8+4];
                float4 bq = *(const float4*)&Rs[m][tx*4];
                float av[8] = {a0.x,a0.y,a0.z,a0.w,a1.x,a1.y,a1.z,a1.w};
                float bvv[4] = {bq.x,bq.y,bq.z,bq.w};
                #pragma unroll
                for (int i = 0; i < 8; i++)
                    #pragma unroll
                    for (int j = 0; j < 4; j++) acc[i][j] += av[i] * bvv[j];
            }
            __syncthreads();
        }
    }
    float* ob = ofull + (size_t)b * (Nn * Cc) + (size_t)h * (Nn * HDd);
    #pragma unroll
    for (int i = 0; i < 8; i++) {
        int gi = i0 + ty*8 + i;
        if (gi < Nn)
            *(float4*)(ob + (size_t)gi * HDd + tx*4) =
                make_float4(acc[i][0], acc[i][1], acc[i][2], acc[i][3]);
    }
}

extern "C" void kernel_launch(void* const* d_in, const int* in_sizes, int n_in,
                              void* d_out, int out_size) {
    const float* x       = (const float*)d_in[0];
    const float* anchors = (const float*)d_in[1];
    const float* weights = (const float*)d_in[2];
    const float* Wqk     = (const float*)d_in[3];
    const float* Wqk2    = (const float*)d_in[4];
    const float* Wv      = (const float*)d_in[5];
    const float* Wproj   = (const float*)d_in[6];
    const float* bproj   = (const float*)d_in[7];

    float* out  = (float*)d_out;                 // (B,N,C)
    float* left = out + (size_t)Bb * Nn * Cc;    // left_attn

    float *xq, *xq2, *xv, *aq, *aq2, *rv, *of0, *of1;
    cudaGetSymbolAddress((void**)&xq,  g_xq);
    cudaGetSymbolAddress((void**)&xq2, g_xq2);
    cudaGetSymbolAddress((void**)&xv,  g_xv);
    cudaGetSymbolAddress((void**)&aq,  g_aq);
    cudaGetSymbolAddress((void**)&aq2, g_aq2);
    cudaGetSymbolAddress((void**)&rv,  g_rv);
    cudaGetSymbolAddress((void**)&of0, g_of0);
    cudaGetSymbolAddress((void**)&of1, g_of1);

    const int MX = Bb * Nn;    // 1568
    const int MA = NCc * Nn;   // 1960

    // x projections (Wqk, Wqk2, Wv) in one launch
    gemm_multi<<<dim3((MX+63)/64, 8, 3), 128>>>(x, nullptr, Wqk, Wqk2, Wv,
                                                xq, xq2, xv, nullptr, MX);
    // anchor projections (Wqk, Wqk2)
    gemm_multi<<<dim3((MA+63)/64, 8, 2), 128>>>(anchors, nullptr, Wqk, Wqk2, Wqk,
                                                aq, aq2, aq, nullptr, MA);
    // left_attn straight into the output buffer
    attn_left_kernel<<<dim3(16, NBATCH), 128>>>(xq, aq, left);
    // fused right-attn + RV (static 48KB smem, no attribute calls)
    right_rv_kernel<<<dim3(4, NBATCH), 128>>>(xq2, aq2, xv, rv);
    // weighted combine, c split into two partials
    combine_kernel<<<dim3(4, Bb*Hh, 2), 128>>>(left, weights, rv, of0, of1);
    // final projection: A = of0 + of1, plus bias
    gemm_multi<<<dim3((MX+63)/64, 8, 1), 128>>>(of0, of1, Wproj, Wproj, Wproj,
                                                out, out, out, bproj, MX);
}

// round 13
// speedup vs baseline: 2.5988x; 1.5589x over previous
#include <cuda_runtime.h>
#include <cuda_bf16.h>
#include <cstddef>
#include <cstdint>

#define Bb 8
#define Nn 196
#define Cc 512
#define NCc 10
#define Hh 8
#define HDd 64
#define SCALE 0.125f
#define NBATCH (Bb*NCc*Hh)
#define ATT_SZ (Nn*Nn)
#define RV_SZ (Nn*HDd)

__device__ float g_xq   [Bb*Nn*Cc];
__device__ float g_xq2  [Bb*Nn*Cc];
__device__ float g_xv   [Bb*Nn*Cc];
__device__ float g_aq   [NCc*Nn*Cc];
__device__ float g_aq2  [NCc*Nn*Cc];
__device__ float g_rv   [NBATCH*RV_SZ];
__device__ float g_of0  [Bb*Nn*Cc];
__device__ float g_of1  [Bb*Nn*Cc];

#define F4(p) (*(const float4*)(p))
static __device__ __forceinline__ float4 f4zero() { return make_float4(0.f,0.f,0.f,0.f); }

static __device__ __forceinline__ uint32_t s2u(const void* p) {
    uint32_t a;
    asm("{ .reg .u64 t; cvta.to.shared.u64 t, %1; cvt.u32.u64 %0, t; }" : "=r"(a) : "l"(p));
    return a;
}
static __device__ __forceinline__ unsigned pk2(float a, float b) {
    __nv_bfloat162 t; t.x = __float2bfloat16(a); t.y = __float2bfloat16(b);
    return *reinterpret_cast<unsigned*>(&t);
}
static __device__ __forceinline__ float lo1(float x) {
    return x - __bfloat162float(__float2bfloat16(x));
}
#define SWZ(o) ((o) ^ (((o) >> 3) & 0x70))

#define LDSM_X4(r, a) \
    asm volatile("ldmatrix.sync.aligned.m8n8.x4.shared.b16 {%0,%1,%2,%3}, [%4];" \
        : "=r"((r)[0]),"=r"((r)[1]),"=r"((r)[2]),"=r"((r)[3]) : "r"(a))
#define LDSM_X2(r, a) \
    asm volatile("ldmatrix.sync.aligned.m8n8.x2.shared.b16 {%0,%1}, [%2];" \
        : "=r"((r)[0]),"=r"((r)[1]) : "r"(a))
#define LDSM_X2T(r, a) \
    asm volatile("ldmatrix.sync.aligned.m8n8.x2.trans.shared.b16 {%0,%1}, [%2];" \
        : "=r"((r)[0]),"=r"((r)[1]) : "r"(a))
#define MMA_BF16(c, a, b) \
    asm volatile("mma.sync.aligned.m16n8k16.row.col.f32.bf16.bf16.f32 " \
        "{%0,%1,%2,%3}, {%4,%5,%6,%7}, {%8,%9}, {%0,%1,%2,%3};" \
        : "+f"((c)[0]),"+f"((c)[1]),"+f"((c)[2]),"+f"((c)[3]) \
        : "r"((a)[0]),"r"((a)[1]),"r"((a)[2]),"r"((a)[3]), "r"((b)[0]),"r"((b)[1]))

// SMEM: A_hi 0..16K, A_lo 16K..32K (128 rows x 128B, SW128-swizzled)
//       B_hi 32K..40K, B_lo 40K..48K (64 rows x 128B) - B chunk, reused for V
#define SA_H 0
#define SA_L 16384
#define SB_H 32768
#define SB_L 40960

// Shared staging helpers -----------------------------------------------------
static __device__ __forceinline__ void stageA(unsigned char* SM, const float* Ab,
                                              int tid, int mt) {
    int r = tid >> 1, half = tid & 1;
    int gr = mt * 128 + r;
    #pragma unroll
    for (int q = 0; q < 8; q++) {
        float4 v = (gr < Nn) ? F4(Ab + (size_t)gr * Cc + half*32 + q*4) : f4zero();
        int off = r*128 + half*64 + q*8;
        *(uint2*)(SM + SA_H + SWZ(off)) = make_uint2(pk2(v.x, v.y), pk2(v.z, v.w));
        *(uint2*)(SM + SA_L + SWZ(off)) =
            make_uint2(pk2(lo1(v.x), lo1(v.y)), pk2(lo1(v.z), lo1(v.w)));
    }
}
static __device__ __forceinline__ void stageB(unsigned char* SM, const float* Bp,
                                              int tid, int j0) {
    int r = tid >> 2, q4 = tid & 3;
    int gj = j0 + r;
    #pragma unroll
    for (int q = 0; q < 4; q++) {
        float4 v = (gj < Nn) ? F4(Bp + (size_t)gj * Cc + q4*16 + q*4) : f4zero();
        int off = r*128 + q4*32 + q*8;
        *(uint2*)(SM + SB_H + SWZ(off)) = make_uint2(pk2(v.x, v.y), pk2(v.z, v.w));
        *(uint2*)(SM + SB_L + SWZ(off)) =
            make_uint2(pk2(lo1(v.x), lo1(v.y)), pk2(lo1(v.z), lo1(v.w)));
    }
}
// MMA1: acc1 = Ah.Bh + Ah.Bl + Al.Bh over K=64, then relu*sc.
static __device__ __forceinline__ void mma1(uint32_t sb, int wr, int lane,
                                            float sc, float acc1[8][4]) {
    #pragma unroll
    for (int n = 0; n < 8; n++)
        #pragma unroll
        for (int j = 0; j < 4; j++) acc1[n][j] = 0.f;
    #pragma unroll
    for (int ks = 0; ks < 4; ks++) {
        int arow = wr + (lane & 15);
        int acolb = ks*32 + ((lane >> 4) << 4);
        uint32_t ah[4], al[4];
        LDSM_X4(ah, sb + SA_H + SWZ(arow*128 + acolb));
        LDSM_X4(al, sb + SA_L + SWZ(arow*128 + acolb));
        #pragma unroll
        for (int n = 0; n < 8; n++) {
            int brow = n*8 + (lane & 7);
            int bcolb = ks*32 + (((lane >> 3) & 1) << 4);
            uint32_t bh[2], bl[2];
            LDSM_X2(bh, sb + SB_H + SWZ(brow*128 + bcolb));
            LDSM_X2(bl, sb + SB_L + SWZ(brow*128 + bcolb));
            MMA_BF16(acc1[n], ah, bh);
            MMA_BF16(acc1[n], ah, bl);
            MMA_BF16(acc1[n], al, bh);
        }
    }
    #pragma unroll
    for (int n = 0; n < 8; n++)
        #pragma unroll
        for (int j = 0; j < 4; j++) acc1[n][j] = fmaxf(acc1[n][j] * sc, 0.f);
}

// ----------------------------------------------------------------------------
// left_attn: out[batch][i][j] = relu(-SCALE * xq[b]_i . aq[c]_j)
// grid = (2 m-tiles, 640 batches), 256 threads (8 warps x 16 i-rows).
// ----------------------------------------------------------------------------
__global__ __launch_bounds__(256) void attn_left_mma(
    const float* __restrict__ Pa, const float* __restrict__ Pb,
    float* __restrict__ out)
{
    __shared__ __align__(16) unsigned char SM[49152];
    int tid = threadIdx.x, lane = tid & 31, warp = tid >> 5;
    int mt = blockIdx.x, batch = blockIdx.y;
    int h = batch & 7, c = (batch >> 3) % 10, b = batch / 80;
    const float* Ab = Pa + (size_t)b * Nn * Cc + h * HDd;
    const float* Bp = Pb + (size_t)c * Nn * Cc + h * HDd;
    uint32_t sb = s2u(SM);

    stageA(SM, Ab, tid, mt);
    int wr = warp * 16, g = lane >> 2, t = lane & 3;

    for (int ch = 0; ch < 4; ch++) {
        int j0 = ch * 64;
        __syncthreads();
        stageB(SM, Bp, tid, j0);
        __syncthreads();
        float acc1[8][4];
        mma1(sb, wr, lane, -SCALE, acc1);
        int row0 = mt*128 + wr + g;
        float* ob = out + (size_t)batch * ATT_SZ;
        #pragma unroll
        for (int n = 0; n < 8; n++) {
            int col = j0 + n*8 + 2*t;
            if (col < Nn) {
                if (row0 < Nn)
                    *(float2*)(ob + (size_t)row0 * Nn + col) =
                        make_float2(acc1[n][0], acc1[n][1]);
                if (row0 + 8 < Nn)
                    *(float2*)(ob + (size_t)(row0+8) * Nn + col) =
                        make_float2(acc1[n][2], acc1[n][3]);
            }
        }
    }
}

// ----------------------------------------------------------------------------
// fused right-attn + RV: out[batch][i][d] =
//   sum_j relu(SCALE * aq2[c]_i . xq2[b]_j) * xv[b][j][d]
// S converted to A-fragments in registers (D frag layout == A frag layout).
// ----------------------------------------------------------------------------
__global__ __launch_bounds__(256) void attn_rv_mma(
    const float* __restrict__ Pa, const float* __restrict__ Pb,
    const float* __restrict__ Vsrc, float* __restrict__ out)
{
    __shared__ __align__(16) unsigned char SM[49152];
    int tid = threadIdx.x, lane = tid & 31, warp = tid >> 5;
    int mt = blockIdx.x, batch = blockIdx.y;
    int h = batch & 7, c = (batch >> 3) % 10, b = batch / 80;
    const float* Ab = Pa + (size_t)c * Nn * Cc + h * HDd;
    const float* Bp = Pb + (size_t)b * Nn * Cc + h * HDd;
    const float* Vb = Vsrc + (size_t)b * Nn * Cc + h * HDd;
    uint32_t sb = s2u(SM);

    stageA(SM, Ab, tid, mt);
    int wr = warp * 16, g = lane >> 2, t = lane & 3;

    float acc2[8][4];
    #pragma unroll
    for (int n = 0; n < 8; n++)
        #pragma unroll
        for (int j = 0; j < 4; j++) acc2[n][j] = 0.f;

    for (int ch = 0; ch < 4; ch++) {
        int j0 = ch * 64;
        __syncthreads();
        stageB(SM, Bp, tid, j0);
        __syncthreads();
        float acc1[8][4];
        mma1(sb, wr, lane, SCALE, acc1);

        __syncthreads();                 // all warps done reading SB (Q2)
        stageB(SM, Vb, tid, j0);         // restage SB with V chunk
        __syncthreads();

        #pragma unroll
        for (int ks = 0; ks < 4; ks++) {
            uint32_t sh[4], sl[4];
            sh[0] = pk2(acc1[2*ks][0],   acc1[2*ks][1]);
            sh[1] = pk2(acc1[2*ks][2],   acc1[2*ks][3]);
            sh[2] = pk2(acc1[2*ks+1][0], acc1[2*ks+1][1]);
            sh[3] = pk2(acc1[2*ks+1][2], acc1[2*ks+1][3]);
            sl[0] = pk2(lo1(acc1[2*ks][0]),   lo1(acc1[2*ks][1]));
            sl[1] = pk2(lo1(acc1[2*ks][2]),   lo1(acc1[2*ks][3]));
            sl[2] = pk2(lo1(acc1[2*ks+1][0]), lo1(acc1[2*ks+1][1]));
            sl[3] = pk2(lo1(acc1[2*ks+1][2]), lo1(acc1[2*ks+1][3]));
            #pragma unroll
            for (int n = 0; n < 8; n++) {
                int vrow = ks*16 + (lane & 15);   // j rows
                int vcolb = n*16;                 // d block (8 bf16 = 16B)
                uint32_t vh[2], vl[2];
                LDSM_X2T(vh, sb + SB_H + SWZ(vrow*128 + vcolb));
                LDSM_X2T(vl, sb + SB_L + SWZ(vrow*128 + vcolb));
                MMA_BF16(acc2[n], sh, vh);
                MMA_BF16(acc2[n], sh, vl);
                MMA_BF16(acc2[n], sl, vh);
            }
        }
    }

    int row0 = mt*128 + wr + g;
    float* rb = out + (size_t)batch * RV_SZ;
    #pragma unroll
    for (int n = 0; n < 8; n++) {
        int d = n*8 + 2*t;
        if (row0 < Nn)
            *(float2*)(rb + (size_t)row0 * HDd + d) =
                make_float2(acc2[n][0], acc2[n][1]);
        if (row0 + 8 < Nn)
            *(float2*)(rb + (size_t)(row0+8) * HDd + d) =
                make_float2(acc2[n][2], acc2[n][3]);
    }
}

// ----------------------------------------------------------------------------
// GEMM: O[M,512] = (A (+A2))[M,512] @ W[512,512] (+bias). (proven SIMT)
// ----------------------------------------------------------------------------
__global__ __launch_bounds__(128) void gemm_multi(
    const float* __restrict__ A, const float* __restrict__ A2,
    const float* __restrict__ W0, const float* __restrict__ W1, const float* __restrict__ W2,
    float* __restrict__ O0, float* __restrict__ O1, float* __restrict__ O2,
    const float* __restrict__ bias, int M)
{
    __shared__ __align__(16) float Asm[32][68];
    __shared__ __align__(16) float Bsm[32][68];
    int z = blockIdx.z;
    const float* W = (z == 0) ? W0 : (z == 1 ? W1 : W2);
    float*       O = (z == 0) ? O0 : (z == 1 ? O1 : O2);
    int tid = threadIdx.x, tx = tid & 15, ty = tid >> 4;
    int row0 = blockIdx.x * 64, col0 = blockIdx.y * 64;
    float acc[8][4] = {};
    for (int k0 = 0; k0 < 512; k0 += 32) {
        #pragma unroll
        for (int u = 0; u < 4; u++) {
            int f = tid + u * 128;
            int r = f >> 3, q = f & 7;
            float4 v = f4zero();
            if (row0 + r < M) {
                v = F4(A + (size_t)(row0 + r) * 512 + k0 + q * 4);
                if (A2) {
                    float4 v2 = F4(A2 + (size_t)(row0 + r) * 512 + k0 + q * 4);
                    v.x += v2.x; v.y += v2.y; v.z += v2.z; v.w += v2.w;
                }
            }
            Asm[q*4+0][r] = v.x; Asm[q*4+1][r] = v.y;
            Asm[q*4+2][r] = v.z; Asm[q*4+3][r] = v.w;
        }
        #pragma unroll
        for (int u = 0; u < 4; u++) {
            int f = tid + u * 128;
            int kk = f >> 4, q = f & 15;
            *(float4*)&Bsm[kk][q*4] = F4(W + (size_t)(k0 + kk) * 512 + col0 + q * 4);
        }
        __syncthreads();
        #pragma unroll
        for (int kk = 0; kk < 32; kk++) {
            float4 a0 = *(const float4*)&Asm[kk][ty*8];
            float4 a1 = *(const float4*)&Asm[kk][ty*8+4];
            float4 b  = *(const float4*)&Bsm[kk][tx*4];
            float av[8] = {a0.x,a0.y,a0.z,a0.w,a1.x,a1.y,a1.z,a1.w};
            float bv[4] = {b.x,b.y,b.z,b.w};
            #pragma unroll
            for (int i = 0; i < 8; i++)
                #pragma unroll
                for (int j = 0; j < 4; j++) acc[i][j] += av[i] * bv[j];
        }
        __syncthreads();
    }
    float4 bv4 = bias ? F4(bias + col0 + tx*4) : f4zero();
    #pragma unroll
    for (int i = 0; i < 8; i++) {
        int r = row0 + ty*8 + i;
        if (r < M)
            *(float4*)(O + (size_t)r * 512 + col0 + tx*4) =
                make_float4(acc[i][0]+bv4.x, acc[i][1]+bv4.y,
                            acc[i][2]+bv4.z, acc[i][3]+bv4.w);
    }
}

// ----------------------------------------------------------------------------
// combine: of_z[b,h,i,d] = sum_{c in z-group} w[b,h,c] * (L_c @ RV_c)[i,d]
// ----------------------------------------------------------------------------
__global__ __launch_bounds__(128) void combine_kernel(
    const float* __restrict__ left, const float* __restrict__ w,
    const float* __restrict__ rv, float* __restrict__ of0, float* __restrict__ of1)
{
    __shared__ __align__(16) float Ls[64][68];
    __shared__ __align__(16) float Rs[64][68];
    int bh = blockIdx.y;
    int b = bh >> 3, h = bh & 7;
    int i0 = blockIdx.x * 64;
    int z = blockIdx.z;
    float* ofull = z ? of1 : of0;
    int tid = threadIdx.x, tx = tid & 15, ty = tid >> 4;
    float acc[8][4] = {};
    for (int cc = 0; cc < 5; cc++) {
        int c = z * 5 + cc;
        float wc = w[(b * Hh + h) * NCc + c];
        int batch = (b * NCc + c) * Hh + h;
        const float* Lb = left + (size_t)batch * ATT_SZ;
        const float* Rb = rv + (size_t)batch * RV_SZ;
        for (int m0 = 0; m0 < 256; m0 += 64) {
            #pragma unroll
            for (int u = 0; u < 8; u++) {
                int f = tid + u * 128;
                int r = f >> 4, q = f & 15;
                float4 v = (i0 + r < Nn && m0 + q*4 < Nn)
                         ? F4(Lb + (size_t)(i0 + r) * Nn + m0 + q*4) : f4zero();
                Ls[q*4+0][r] = v.x * wc; Ls[q*4+1][r] = v.y * wc;
                Ls[q*4+2][r] = v.z * wc; Ls[q*4+3][r] = v.w * wc;
                float4 rvv = (m0 + r < Nn)
                         ? F4(Rb + (size_t)(m0 + r) * HDd + q*4) : f4zero();
                *(float4*)&Rs[r][q*4] = rvv;
            }
            __syncthreads();
            #pragma unroll
            for (int m = 0; m < 64; m++) {
                float4 a0 = *(const float4*)&Ls[m][ty*8];
                float4 a1 = *(const float4*)&Ls[m][ty*8+4];
                float4 bq = *(const float4*)&Rs[m][tx*4];
                float av[8] = {a0.x,a0.y,a0.z,a0.w,a1.x,a1.y,a1.z,a1.w};
                float bvv[4] = {bq.x,bq.y,bq.z,bq.w};
                #pragma unroll
                for (int i = 0; i < 8; i++)
                    #pragma unroll
                    for (int j = 0; j < 4; j++) acc[i][j] += av[i] * bvv[j];
            }
            __syncthreads();
        }
    }
    float* ob = ofull + (size_t)b * (Nn * Cc) + (size_t)h * (Nn * HDd);
    #pragma unroll
    for (int i = 0; i < 8; i++) {
        int gi = i0 + ty*8 + i;
        if (gi < Nn)
            *(float4*)(ob + (size_t)gi * HDd + tx*4) =
                make_float4(acc[i][0], acc[i][1], acc[i][2], acc[i][3]);
    }
}

extern "C" void kernel_launch(void* const* d_in, const int* in_sizes, int n_in,
                              void* d_out, int out_size) {
    const float* x       = (const float*)d_in[0];
    const float* anchors = (const float*)d_in[1];
    const float* weights = (const float*)d_in[2];
    const float* Wqk     = (const float*)d_in[3];
    const float* Wqk2    = (const float*)d_in[4];
    const float* Wv      = (const float*)d_in[5];
    const float* Wproj   = (const float*)d_in[6];
    const float* bproj   = (const float*)d_in[7];

    float* out  = (float*)d_out;
    float* left = out + (size_t)Bb * Nn * Cc;

    float *xq, *xq2, *xv, *aq, *aq2, *rv, *of0, *of1;
    cudaGetSymbolAddress((void**)&xq,  g_xq);
    cudaGetSymbolAddress((void**)&xq2, g_xq2);
    cudaGetSymbolAddress((void**)&xv,  g_xv);
    cudaGetSymbolAddress((void**)&aq,  g_aq);
    cudaGetSymbolAddress((void**)&aq2, g_aq2);
    cudaGetSymbolAddress((void**)&rv,  g_rv);
    cudaGetSymbolAddress((void**)&of0, g_of0);
    cudaGetSymbolAddress((void**)&of1, g_of1);

    const int MX = Bb * Nn;    // 1568
    const int MA = NCc * Nn;   // 1960

    gemm_multi<<<dim3((MX+63)/64, 8, 3), 128>>>(x, nullptr, Wqk, Wqk2, Wv,
                                                xq, xq2, xv, nullptr, MX);
    gemm_multi<<<dim3((MA+63)/64, 8, 2), 128>>>(anchors, nullptr, Wqk, Wqk2, Wqk,
                                                aq, aq2, aq, nullptr, MA);
    // left_attn (HMMA): A rows = xq[b], B rows = aq[c]
    attn_left_mma<<<dim3(2, NBATCH), 256>>>(xq, aq, left);
    // fused right-attn + RV (HMMA): A rows = aq2[c], B rows = xq2[b], V = xv[b]
    attn_rv_mma<<<dim3(2, NBATCH), 256>>>(aq2, xq2, xv, rv);
    combine_kernel<<<dim3(4, Bb*Hh, 2), 128>>>(left, weights, rv, of0, of1);
    gemm_multi<<<dim3((MX+63)/64, 8, 1), 128>>>(of0, of1, Wproj, Wproj, Wproj,
                                                out, out, out, bproj, MX);
}

// round 14
// speedup vs baseline: 3.0310x; 1.1663x over previous
#include <cuda_runtime.h>
#include <cuda_bf16.h>
#include <cstddef>
#include <cstdint>

#define Bb 8
#define Nn 196
#define Cc 512
#define NCc 10
#define Hh 8
#define HDd 64
#define SCALE 0.125f
#define NBATCH (Bb*NCc*Hh)
#define ATT_SZ (Nn*Nn)
#define RV_SZ (Nn*HDd)

__device__ float g_xq   [Bb*Nn*Cc];
__device__ float g_xq2  [Bb*Nn*Cc];
__device__ float g_xv   [Bb*Nn*Cc];
__device__ float g_aq   [NCc*Nn*Cc];
__device__ float g_aq2  [NCc*Nn*Cc];
__device__ float g_rv   [NBATCH*RV_SZ];
__device__ float g_of0  [Bb*Nn*Cc];
__device__ float g_of1  [Bb*Nn*Cc];

#define F4(p) (*(const float4*)(p))
static __device__ __forceinline__ float4 f4zero() { return make_float4(0.f,0.f,0.f,0.f); }

static __device__ __forceinline__ uint32_t s2u(const void* p) {
    uint32_t a;
    asm("{ .reg .u64 t; cvta.to.shared.u64 t, %1; cvt.u32.u64 %0, t; }" : "=r"(a) : "l"(p));
    return a;
}
static __device__ __forceinline__ unsigned pk2(float a, float b) {
    __nv_bfloat162 t; t.x = __float2bfloat16(a); t.y = __float2bfloat16(b);
    return *reinterpret_cast<unsigned*>(&t);
}
static __device__ __forceinline__ float lo1(float x) {
    return x - __bfloat162float(__float2bfloat16(x));
}
#define SWZ(o) ((o) ^ (((o) >> 3) & 0x70))

#define LDSM_X4(r, a) \
    asm volatile("ldmatrix.sync.aligned.m8n8.x4.shared.b16 {%0,%1,%2,%3}, [%4];" \
        : "=r"((r)[0]),"=r"((r)[1]),"=r"((r)[2]),"=r"((r)[3]) : "r"(a))
#define LDSM_X2(r, a) \
    asm volatile("ldmatrix.sync.aligned.m8n8.x2.shared.b16 {%0,%1}, [%2];" \
        : "=r"((r)[0]),"=r"((r)[1]) : "r"(a))
#define LDSM_X2T(r, a) \
    asm volatile("ldmatrix.sync.aligned.m8n8.x2.trans.shared.b16 {%0,%1}, [%2];" \
        : "=r"((r)[0]),"=r"((r)[1]) : "r"(a))
#define MMA_BF16(c, a, b) \
    asm volatile("mma.sync.aligned.m16n8k16.row.col.f32.bf16.bf16.f32 " \
        "{%0,%1,%2,%3}, {%4,%5,%6,%7}, {%8,%9}, {%0,%1,%2,%3};" \
        : "+f"((c)[0]),"+f"((c)[1]),"+f"((c)[2]),"+f"((c)[3]) \
        : "r"((a)[0]),"r"((a)[1]),"r"((a)[2]),"r"((a)[3]), "r"((b)[0]),"r"((b)[1]))

// SMEM: A_hi 0..16K, A_lo 16K..32K (128 rows x 128B, SW128-swizzled)
//       B_hi 32K..40K, B_lo 40K..48K (64 rows x 128B)
#define SA_H 0
#define SA_L 16384
#define SB_H 32768
#define SB_L 40960

// Shared staging helpers -----------------------------------------------------
static __device__ __forceinline__ void stageA(unsigned char* SM, const float* Ab,
                                              int tid, int mt) {
    int r = tid >> 1, half = tid & 1;
    int gr = mt * 128 + r;
    #pragma unroll
    for (int q = 0; q < 8; q++) {
        float4 v = (gr < Nn) ? F4(Ab + (size_t)gr * Cc + half*32 + q*4) : f4zero();
        int off = r*128 + half*64 + q*8;
        *(uint2*)(SM + SA_H + SWZ(off)) = make_uint2(pk2(v.x, v.y), pk2(v.z, v.w));
        *(uint2*)(SM + SA_L + SWZ(off)) =
            make_uint2(pk2(lo1(v.x), lo1(v.y)), pk2(lo1(v.z), lo1(v.w)));
    }
}
static __device__ __forceinline__ void stageB(unsigned char* SM, const float* Bp,
                                              int tid, int j0) {
    int r = tid >> 2, q4 = tid & 3;
    int gj = j0 + r;
    #pragma unroll
    for (int q = 0; q < 4; q++) {
        float4 v = (gj < Nn) ? F4(Bp + (size_t)gj * Cc + q4*16 + q*4) : f4zero();
        int off = r*128 + q4*32 + q*8;
        *(uint2*)(SM + SB_H + SWZ(off)) = make_uint2(pk2(v.x, v.y), pk2(v.z, v.w));
        *(uint2*)(SM + SB_L + SWZ(off)) =
            make_uint2(pk2(lo1(v.x), lo1(v.y)), pk2(lo1(v.z), lo1(v.w)));
    }
}
// MMA1: acc1 = Ah.Bh + Ah.Bl + Al.Bh over K=64, then relu*sc.
static __device__ __forceinline__ void mma1(uint32_t sb, int wr, int lane,
                                            float sc, float acc1[8][4]) {
    #pragma unroll
    for (int n = 0; n < 8; n++)
        #pragma unroll
        for (int j = 0; j < 4; j++) acc1[n][j] = 0.f;
    #pragma unroll
    for (int ks = 0; ks < 4; ks++) {
        int arow = wr + (lane & 15);
        int acolb = ks*32 + ((lane >> 4) << 4);
        uint32_t ah[4], al[4];
        LDSM_X4(ah, sb + SA_H + SWZ(arow*128 + acolb));
        LDSM_X4(al, sb + SA_L + SWZ(arow*128 + acolb));
        #pragma unroll
        for (int n = 0; n < 8; n++) {
            int brow = n*8 + (lane & 7);
            int bcolb = ks*32 + (((lane >> 3) & 1) << 4);
            uint32_t bh[2], bl[2];
            LDSM_X2(bh, sb + SB_H + SWZ(brow*128 + bcolb));
            LDSM_X2(bl, sb + SB_L + SWZ(brow*128 + bcolb));
            MMA_BF16(acc1[n], ah, bh);
            MMA_BF16(acc1[n], ah, bl);
            MMA_BF16(acc1[n], al, bh);
        }
    }
    #pragma unroll
    for (int n = 0; n < 8; n++)
        #pragma unroll
        for (int j = 0; j < 4; j++) acc1[n][j] = fmaxf(acc1[n][j] * sc, 0.f);
}

// ----------------------------------------------------------------------------
// left_attn: out[batch][i][j] = relu(-SCALE * xq[b]_i . aq[c]_j)
// ----------------------------------------------------------------------------
__global__ __launch_bounds__(256) void attn_left_mma(
    const float* __restrict__ Pa, const float* __restrict__ Pb,
    float* __restrict__ out)
{
    __shared__ __align__(16) unsigned char SM[49152];
    int tid = threadIdx.x, lane = tid & 31, warp = tid >> 5;
    int mt = blockIdx.x, batch = blockIdx.y;
    int h = batch & 7, c = (batch >> 3) % 10, b = batch / 80;
    const float* Ab = Pa + (size_t)b * Nn * Cc + h * HDd;
    const float* Bp = Pb + (size_t)c * Nn * Cc + h * HDd;
    uint32_t sb = s2u(SM);

    stageA(SM, Ab, tid, mt);
    int wr = warp * 16, g = lane >> 2, t = lane & 3;

    for (int ch = 0; ch < 4; ch++) {
        int j0 = ch * 64;
        __syncthreads();
        stageB(SM, Bp, tid, j0);
        __syncthreads();
        float acc1[8][4];
        mma1(sb, wr, lane, -SCALE, acc1);
        int row0 = mt*128 + wr + g;
        float* ob = out + (size_t)batch * ATT_SZ;
        #pragma unroll
        for (int n = 0; n < 8; n++) {
            int col = j0 + n*8 + 2*t;
            if (col < Nn) {
                if (row0 < Nn)
                    *(float2*)(ob + (size_t)row0 * Nn + col) =
                        make_float2(acc1[n][0], acc1[n][1]);
                if (row0 + 8 < Nn)
                    *(float2*)(ob + (size_t)(row0+8) * Nn + col) =
                        make_float2(acc1[n][2], acc1[n][3]);
            }
        }
    }
}

// ----------------------------------------------------------------------------
// fused right-attn + RV: out[batch][i][d] =
//   sum_j relu(SCALE * aq2[c]_i . xq2[b]_j) * xv[b][j][d]
// ----------------------------------------------------------------------------
__global__ __launch_bounds__(256) void attn_rv_mma(
    const float* __restrict__ Pa, const float* __restrict__ Pb,
    const float* __restrict__ Vsrc, float* __restrict__ out)
{
    __shared__ __align__(16) unsigned char SM[49152];
    int tid = threadIdx.x, lane = tid & 31, warp = tid >> 5;
    int mt = blockIdx.x, batch = blockIdx.y;
    int h = batch & 7, c = (batch >> 3) % 10, b = batch / 80;
    const float* Ab = Pa + (size_t)c * Nn * Cc + h * HDd;
    const float* Bp = Pb + (size_t)b * Nn * Cc + h * HDd;
    const float* Vb = Vsrc + (size_t)b * Nn * Cc + h * HDd;
    uint32_t sb = s2u(SM);

    stageA(SM, Ab, tid, mt);
    int wr = warp * 16, g = lane >> 2, t = lane & 3;

    float acc2[8][4];
    #pragma unroll
    for (int n = 0; n < 8; n++)
        #pragma unroll
        for (int j = 0; j < 4; j++) acc2[n][j] = 0.f;

    for (int ch = 0; ch < 4; ch++) {
        int j0 = ch * 64;
        __syncthreads();
        stageB(SM, Bp, tid, j0);
        __syncthreads();
        float acc1[8][4];
        mma1(sb, wr, lane, SCALE, acc1);

        __syncthreads();                 // all warps done reading SB (Q2)
        stageB(SM, Vb, tid, j0);         // restage SB with V chunk
        __syncthreads();

        #pragma unroll
        for (int ks = 0; ks < 4; ks++) {
            uint32_t sh[4], sl[4];
            sh[0] = pk2(acc1[2*ks][0],   acc1[2*ks][1]);
            sh[1] = pk2(acc1[2*ks][2],   acc1[2*ks][3]);
            sh[2] = pk2(acc1[2*ks+1][0], acc1[2*ks+1][1]);
            sh[3] = pk2(acc1[2*ks+1][2], acc1[2*ks+1][3]);
            sl[0] = pk2(lo1(acc1[2*ks][0]),   lo1(acc1[2*ks][1]));
            sl[1] = pk2(lo1(acc1[2*ks][2]),   lo1(acc1[2*ks][3]));
            sl[2] = pk2(lo1(acc1[2*ks+1][0]), lo1(acc1[2*ks+1][1]));
            sl[3] = pk2(lo1(acc1[2*ks+1][2]), lo1(acc1[2*ks+1][3]));
            #pragma unroll
            for (int n = 0; n < 8; n++) {
                int vrow = ks*16 + (lane & 15);
                int vcolb = n*16;
                uint32_t vh[2], vl[2];
                LDSM_X2T(vh, sb + SB_H + SWZ(vrow*128 + vcolb));
                LDSM_X2T(vl, sb + SB_L + SWZ(vrow*128 + vcolb));
                MMA_BF16(acc2[n], sh, vh);
                MMA_BF16(acc2[n], sh, vl);
                MMA_BF16(acc2[n], sl, vh);
            }
        }
    }

    int row0 = mt*128 + wr + g;
    float* rb = out + (size_t)batch * RV_SZ;
    #pragma unroll
    for (int n = 0; n < 8; n++) {
        int d = n*8 + 2*t;
        if (row0 < Nn)
            *(float2*)(rb + (size_t)row0 * HDd + d) =
                make_float2(acc2[n][0], acc2[n][1]);
        if (row0 + 8 < Nn)
            *(float2*)(rb + (size_t)(row0+8) * HDd + d) =
                make_float2(acc2[n][2], acc2[n][3]);
    }
}

// ----------------------------------------------------------------------------
// HMMA combine: of_z[b,h,i,d] = sum_{c in z-group} w[b,h,c]*(L_c @ RV_c)[i,d]
// A = L chunk (128 i x 64 j) scaled by wc at staging; B = RV chunk via
// ldmatrix.trans (same path as V in attn_rv). fp32 accum across all c/chunks.
// grid = (2 m-tiles, 64 bh, 2 z), 256 threads.
// ----------------------------------------------------------------------------
__global__ __launch_bounds__(256) void combine_mma(
    const float* __restrict__ left, const float* __restrict__ w,
    const float* __restrict__ rv, float* __restrict__ of0, float* __restrict__ of1)
{
    __shared__ __align__(16) unsigned char SM[49152];
    int tid = threadIdx.x, lane = tid & 31, warp = tid >> 5;
    int mt = blockIdx.x;
    int bh = blockIdx.y;
    int b = bh >> 3, h = bh & 7;
    int z = blockIdx.z;
    float* ofull = z ? of1 : of0;
    uint32_t sb = s2u(SM);
    int wr = warp * 16, g = lane >> 2, t = lane & 3;

    float acc[8][4];
    #pragma unroll
    for (int n = 0; n < 8; n++)
        #pragma unroll
        for (int j = 0; j < 4; j++) acc[n][j] = 0.f;

    for (int cc = 0; cc < 5; cc++) {
        int c = z * 5 + cc;
        float wc = w[(b * Hh + h) * NCc + c];
        int batch = (b * NCc + c) * Hh + h;
        const float* Lb = left + (size_t)batch * ATT_SZ;
        const float* Rb = rv + (size_t)batch * RV_SZ;

        for (int ch = 0; ch < 4; ch++) {
            int j0 = ch * 64;
            __syncthreads();
            // stage A = wc * L[mt*128+r][j0..j0+63]  (row stride Nn=196)
            {
                int r = tid >> 1, half = tid & 1;
                int gi = mt * 128 + r;
                #pragma unroll
                for (int q = 0; q < 8; q++) {
                    int col = j0 + half*32 + q*4;
                    float4 v = (gi < Nn && col < Nn)
                             ? F4(Lb + (size_t)gi * Nn + col) : f4zero();
                    v.x *= wc; v.y *= wc; v.z *= wc; v.w *= wc;
                    int off = r*128 + half*64 + q*8;
                    *(uint2*)(SM + SA_H + SWZ(off)) =
                        make_uint2(pk2(v.x, v.y), pk2(v.z, v.w));
                    *(uint2*)(SM + SA_L + SWZ(off)) =
                        make_uint2(pk2(lo1(v.x), lo1(v.y)), pk2(lo1(v.z), lo1(v.w)));
                }
            }
            // stage B = RV[j0+r][0..63]  (row stride HDd=64)
            {
                int r = tid >> 2, q4 = tid & 3;
                int gj = j0 + r;
                #pragma unroll
                for (int q = 0; q < 4; q++) {
                    float4 v = (gj < Nn) ? F4(Rb + (size_t)gj * HDd + q4*16 + q*4)
                                         : f4zero();
                    int off = r*128 + q4*32 + q*8;
                    *(uint2*)(SM + SB_H + SWZ(off)) =
                        make_uint2(pk2(v.x, v.y), pk2(v.z, v.w));
                    *(uint2*)(SM + SB_L + SWZ(off)) =
                        make_uint2(pk2(lo1(v.x), lo1(v.y)), pk2(lo1(v.z), lo1(v.w)));
                }
            }
            __syncthreads();
            // acc += A . B  (A row-major i x k via x4; B k x d via x2.trans)
            #pragma unroll
            for (int ks = 0; ks < 4; ks++) {
                int arow = wr + (lane & 15);
                int acolb = ks*32 + ((lane >> 4) << 4);
                uint32_t ah[4], al[4];
                LDSM_X4(ah, sb + SA_H + SWZ(arow*128 + acolb));
                LDSM_X4(al, sb + SA_L + SWZ(arow*128 + acolb));
                #pragma unroll
                for (int n = 0; n < 8; n++) {
                    int vrow = ks*16 + (lane & 15);
                    int vcolb = n*16;
                    uint32_t vh[2], vl[2];
                    LDSM_X2T(vh, sb + SB_H + SWZ(vrow*128 + vcolb));
                    LDSM_X2T(vl, sb + SB_L + SWZ(vrow*128 + vcolb));
                    MMA_BF16(acc[n], ah, vh);
                    MMA_BF16(acc[n], ah, vl);
                    MMA_BF16(acc[n], al, vh);
                }
            }
        }
    }

    // epilogue: ofull[b, h*N*HD + i*HD + d]
    int row0 = mt*128 + wr + g;
    float* ob = ofull + (size_t)b * (Nn * Cc) + (size_t)h * (Nn * HDd);
    #pragma unroll
    for (int n = 0; n < 8; n++) {
        int d = n*8 + 2*t;
        if (row0 < Nn)
            *(float2*)(ob + (size_t)row0 * HDd + d) =
                make_float2(acc[n][0], acc[n][1]);
        if (row0 + 8 < Nn)
            *(float2*)(ob + (size_t)(row0+8) * HDd + d) =
                make_float2(acc[n][2], acc[n][3]);
    }
}

// ----------------------------------------------------------------------------
// GEMM: O[M,512] = (A (+A2))[M,512] @ W[512,512] (+bias). (proven SIMT)
// ----------------------------------------------------------------------------
__global__ __launch_bounds__(128) void gemm_multi(
    const float* __restrict__ A, const float* __restrict__ A2,
    const float* __restrict__ W0, const float* __restrict__ W1, const float* __restrict__ W2,
    float* __restrict__ O0, float* __restrict__ O1, float* __restrict__ O2,
    const float* __restrict__ bias, int M)
{
    __shared__ __align__(16) float Asm[32][68];
    __shared__ __align__(16) float Bsm[32][68];
    int z = blockIdx.z;
    const float* W = (z == 0) ? W0 : (z == 1 ? W1 : W2);
    float*       O = (z == 0) ? O0 : (z == 1 ? O1 : O2);
    int tid = threadIdx.x, tx = tid & 15, ty = tid >> 4;
    int row0 = blockIdx.x * 64, col0 = blockIdx.y * 64;
    float acc[8][4] = {};
    for (int k0 = 0; k0 < 512; k0 += 32) {
        #pragma unroll
        for (int u = 0; u < 4; u++) {
            int f = tid + u * 128;
            int r = f >> 3, q = f & 7;
            float4 v = f4zero();
            if (row0 + r < M) {
                v = F4(A + (size_t)(row0 + r) * 512 + k0 + q * 4);
                if (A2) {
                    float4 v2 = F4(A2 + (size_t)(row0 + r) * 512 + k0 + q * 4);
                    v.x += v2.x; v.y += v2.y; v.z += v2.z; v.w += v2.w;
                }
            }
            Asm[q*4+0][r] = v.x; Asm[q*4+1][r] = v.y;
            Asm[q*4+2][r] = v.z; Asm[q*4+3][r] = v.w;
        }
        #pragma unroll
        for (int u = 0; u < 4; u++) {
            int f = tid + u * 128;
            int kk = f >> 4, q = f & 15;
            *(float4*)&Bsm[kk][q*4] = F4(W + (size_t)(k0 + kk) * 512 + col0 + q * 4);
        }
        __syncthreads();
        #pragma unroll
        for (int kk = 0; kk < 32; kk++) {
            float4 a0 = *(const float4*)&Asm[kk][ty*8];
            float4 a1 = *(const float4*)&Asm[kk][ty*8+4];
            float4 b  = *(const float4*)&Bsm[kk][tx*4];
            float av[8] = {a0.x,a0.y,a0.z,a0.w,a1.x,a1.y,a1.z,a1.w};
            float bv[4] = {b.x,b.y,b.z,b.w};
            #pragma unroll
            for (int i = 0; i < 8; i++)
                #pragma unroll
                for (int j = 0; j < 4; j++) acc[i][j] += av[i] * bv[j];
        }
        __syncthreads();
    }
    float4 bv4 = bias ? F4(bias + col0 + tx*4) : f4zero();
    #pragma unroll
    for (int i = 0; i < 8; i++) {
        int r = row0 + ty*8 + i;
        if (r < M)
            *(float4*)(O + (size_t)r * 512 + col0 + tx*4) =
                make_float4(acc[i][0]+bv4.x, acc[i][1]+bv4.y,
                            acc[i][2]+bv4.z, acc[i][3]+bv4.w);
    }
}

extern "C" void kernel_launch(void* const* d_in, const int* in_sizes, int n_in,
                              void* d_out, int out_size) {
    const float* x       = (const float*)d_in[0];
    const float* anchors = (const float*)d_in[1];
    const float* weights = (const float*)d_in[2];
    const float* Wqk     = (const float*)d_in[3];
    const float* Wqk2    = (const float*)d_in[4];
    const float* Wv      = (const float*)d_in[5];
    const float* Wproj   = (const float*)d_in[6];
    const float* bproj   = (const float*)d_in[7];

    float* out  = (float*)d_out;
    float* left = out + (size_t)Bb * Nn * Cc;

    float *xq, *xq2, *xv, *aq, *aq2, *rv, *of0, *of1;
    cudaGetSymbolAddress((void**)&xq,  g_xq);
    cudaGetSymbolAddress((void**)&xq2, g_xq2);
    cudaGetSymbolAddress((void**)&xv,  g_xv);
    cudaGetSymbolAddress((void**)&aq,  g_aq);
    cudaGetSymbolAddress((void**)&aq2, g_aq2);
    cudaGetSymbolAddress((void**)&rv,  g_rv);
    cudaGetSymbolAddress((void**)&of0, g_of0);
    cudaGetSymbolAddress((void**)&of1, g_of1);

    const int MX = Bb * Nn;    // 1568
    const int MA = NCc * Nn;   // 1960

    gemm_multi<<<dim3((MX+63)/64, 8, 3), 128>>>(x, nullptr, Wqk, Wqk2, Wv,
                                                xq, xq2, xv, nullptr, MX);
    gemm_multi<<<dim3((MA+63)/64, 8, 2), 128>>>(anchors, nullptr, Wqk, Wqk2, Wqk,
                                                aq, aq2, aq, nullptr, MA);
    attn_left_mma<<<dim3(2, NBATCH), 256>>>(xq, aq, left);
    attn_rv_mma<<<dim3(2, NBATCH), 256>>>(aq2, xq2, xv, rv);
    // HMMA weighted combine, c split z=0:{0..4} -> of0, z=1:{5..9} -> of1
    combine_mma<<<dim3(2, Bb*Hh, 2), 256>>>(left, weights, rv, of0, of1);
    gemm_multi<<<dim3((MX+63)/64, 8, 1), 128>>>(of0, of1, Wproj, Wproj, Wproj,
                                                out, out, out, bproj, MX);
}

// round 15
// speedup vs baseline: 3.0784x; 1.0156x over previous
#include <cuda_runtime.h>
#include <cuda_bf16.h>
#include <cstddef>
#include <cstdint>

#define Bb 8
#define Nn 196
#define Cc 512
#define NCc 10
#define Hh 8
#define HDd 64
#define SCALE 0.125f
#define NBATCH (Bb*NCc*Hh)
#define ATT_SZ (Nn*Nn)
#define RV_SZ (Nn*HDd)

__device__ float g_xq   [Bb*Nn*Cc];
__device__ float g_xq2  [Bb*Nn*Cc];
__device__ float g_xv   [Bb*Nn*Cc];
__device__ float g_aq   [NCc*Nn*Cc];
__device__ float g_aq2  [NCc*Nn*Cc];
__device__ float g_rv   [NBATCH*RV_SZ];
__device__ float g_of0  [Bb*Nn*Cc];
__device__ float g_of1  [Bb*Nn*Cc];

#define F4(p) (*(const float4*)(p))
static __device__ __forceinline__ float4 f4zero() { return make_float4(0.f,0.f,0.f,0.f); }

static __device__ __forceinline__ uint32_t s2u(const void* p) {
    uint32_t a;
    asm("{ .reg .u64 t; cvta.to.shared.u64 t, %1; cvt.u32.u64 %0, t; }" : "=r"(a) : "l"(p));
    return a;
}
static __device__ __forceinline__ unsigned pk2(float a, float b) {
    __nv_bfloat162 t; t.x = __float2bfloat16(a); t.y = __float2bfloat16(b);
    return *reinterpret_cast<unsigned*>(&t);
}
static __device__ __forceinline__ float lo1(float x) {
    return x - __bfloat162float(__float2bfloat16(x));
}
#define SWZ(o) ((o) ^ (((o) >> 3) & 0x70))

#define LDSM_X4(r, a) \
    asm volatile("ldmatrix.sync.aligned.m8n8.x4.shared.b16 {%0,%1,%2,%3}, [%4];" \
        : "=r"((r)[0]),"=r"((r)[1]),"=r"((r)[2]),"=r"((r)[3]) : "r"(a))
#define LDSM_X2(r, a) \
    asm volatile("ldmatrix.sync.aligned.m8n8.x2.shared.b16 {%0,%1}, [%2];" \
        : "=r"((r)[0]),"=r"((r)[1]) : "r"(a))
#define LDSM_X2T(r, a) \
    asm volatile("ldmatrix.sync.aligned.m8n8.x2.trans.shared.b16 {%0,%1}, [%2];" \
        : "=r"((r)[0]),"=r"((r)[1]) : "r"(a))
#define MMA_BF16(c, a, b) \
    asm volatile("mma.sync.aligned.m16n8k16.row.col.f32.bf16.bf16.f32 " \
        "{%0,%1,%2,%3}, {%4,%5,%6,%7}, {%8,%9}, {%0,%1,%2,%3};" \
        : "+f"((c)[0]),"+f"((c)[1]),"+f"((c)[2]),"+f"((c)[3]) \
        : "r"((a)[0]),"r"((a)[1]),"r"((a)[2]),"r"((a)[3]), "r"((b)[0]),"r"((b)[1]))

// SMEM: A_hi 0..16K, A_lo 16K..32K (128 rows x 128B, SW128-swizzled)
//       B_hi 32K..40K, B_lo 40K..48K (64 rows x 128B)
#define SA_H 0
#define SA_L 16384
#define SB_H 32768
#define SB_L 40960

// Shared staging helpers -----------------------------------------------------
static __device__ __forceinline__ void stageA(unsigned char* SM, const float* Ab,
                                              int tid, int mt) {
    int r = tid >> 1, half = tid & 1;
    int gr = mt * 128 + r;
    #pragma unroll
    for (int q = 0; q < 8; q++) {
        float4 v = (gr < Nn) ? F4(Ab + (size_t)gr * Cc + half*32 + q*4) : f4zero();
        int off = r*128 + half*64 + q*8;
        *(uint2*)(SM + SA_H + SWZ(off)) = make_uint2(pk2(v.x, v.y), pk2(v.z, v.w));
        *(uint2*)(SM + SA_L + SWZ(off)) =
            make_uint2(pk2(lo1(v.x), lo1(v.y)), pk2(lo1(v.z), lo1(v.w)));
    }
}
static __device__ __forceinline__ void stageB(unsigned char* SM, const float* Bp,
                                              int tid, int j0) {
    int r = tid >> 2, q4 = tid & 3;
    int gj = j0 + r;
    #pragma unroll
    for (int q = 0; q < 4; q++) {
        float4 v = (gj < Nn) ? F4(Bp + (size_t)gj * Cc + q4*16 + q*4) : f4zero();
        int off = r*128 + q4*32 + q*8;
        *(uint2*)(SM + SB_H + SWZ(off)) = make_uint2(pk2(v.x, v.y), pk2(v.z, v.w));
        *(uint2*)(SM + SB_L + SWZ(off)) =
            make_uint2(pk2(lo1(v.x), lo1(v.y)), pk2(lo1(v.z), lo1(v.w)));
    }
}
// MMA1: acc1 = Ah.Bh + Ah.Bl + Al.Bh over K=64, then relu*sc.
static __device__ __forceinline__ void mma1(uint32_t sb, int wr, int lane,
                                            float sc, float acc1[8][4]) {
    #pragma unroll
    for (int n = 0; n < 8; n++)
        #pragma unroll
        for (int j = 0; j < 4; j++) acc1[n][j] = 0.f;
    #pragma unroll
    for (int ks = 0; ks < 4; ks++) {
        int arow = wr + (lane & 15);
        int acolb = ks*32 + ((lane >> 4) << 4);
        uint32_t ah[4], al[4];
        LDSM_X4(ah, sb + SA_H + SWZ(arow*128 + acolb));
        LDSM_X4(al, sb + SA_L + SWZ(arow*128 + acolb));
        #pragma unroll
        for (int n = 0; n < 8; n++) {
            int brow = n*8 + (lane & 7);
            int bcolb = ks*32 + (((lane >> 3) & 1) << 4);
            uint32_t bh[2], bl[2];
            LDSM_X2(bh, sb + SB_H + SWZ(brow*128 + bcolb));
            LDSM_X2(bl, sb + SB_L + SWZ(brow*128 + bcolb));
            MMA_BF16(acc1[n], ah, bh);
            MMA_BF16(acc1[n], ah, bl);
            MMA_BF16(acc1[n], al, bh);
        }
    }
    #pragma unroll
    for (int n = 0; n < 8; n++)
        #pragma unroll
        for (int j = 0; j < 4; j++) acc1[n][j] = fmaxf(acc1[n][j] * sc, 0.f);
}

// ----------------------------------------------------------------------------
// left_attn: out[batch][i][j] = relu(-SCALE * xq[b]_i . aq[c]_j)
// ----------------------------------------------------------------------------
__global__ __launch_bounds__(256, 2) void attn_left_mma(
    const float* __restrict__ Pa, const float* __restrict__ Pb,
    float* __restrict__ out)
{
    __shared__ __align__(16) unsigned char SM[49152];
    int tid = threadIdx.x, lane = tid & 31, warp = tid >> 5;
    int mt = blockIdx.x, batch = blockIdx.y;
    int h = batch & 7, c = (batch >> 3) % 10, b = batch / 80;
    const float* Ab = Pa + (size_t)b * Nn * Cc + h * HDd;
    const float* Bp = Pb + (size_t)c * Nn * Cc + h * HDd;
    uint32_t sb = s2u(SM);

    stageA(SM, Ab, tid, mt);
    int wr = warp * 16, g = lane >> 2, t = lane & 3;

    for (int ch = 0; ch < 4; ch++) {
        int j0 = ch * 64;
        __syncthreads();
        stageB(SM, Bp, tid, j0);
        __syncthreads();
        float acc1[8][4];
        mma1(sb, wr, lane, -SCALE, acc1);
        int row0 = mt*128 + wr + g;
        float* ob = out + (size_t)batch * ATT_SZ;
        #pragma unroll
        for (int n = 0; n < 8; n++) {
            int col = j0 + n*8 + 2*t;
            if (col < Nn) {
                if (row0 < Nn)
                    *(float2*)(ob + (size_t)row0 * Nn + col) =
                        make_float2(acc1[n][0], acc1[n][1]);
                if (row0 + 8 < Nn)
                    *(float2*)(ob + (size_t)(row0+8) * Nn + col) =
                        make_float2(acc1[n][2], acc1[n][3]);
            }
        }
    }
}

// ----------------------------------------------------------------------------
// fused right-attn + RV: out[batch][i][d] =
//   sum_j relu(SCALE * aq2[c]_i . xq2[b]_j) * xv[b][j][d]
// ----------------------------------------------------------------------------
__global__ __launch_bounds__(256, 2) void attn_rv_mma(
    const float* __restrict__ Pa, const float* __restrict__ Pb,
    const float* __restrict__ Vsrc, float* __restrict__ out)
{
    __shared__ __align__(16) unsigned char SM[49152];
    int tid = threadIdx.x, lane = tid & 31, warp = tid >> 5;
    int mt = blockIdx.x, batch = blockIdx.y;
    int h = batch & 7, c = (batch >> 3) % 10, b = batch / 80;
    const float* Ab = Pa + (size_t)c * Nn * Cc + h * HDd;
    const float* Bp = Pb + (size_t)b * Nn * Cc + h * HDd;
    const float* Vb = Vsrc + (size_t)b * Nn * Cc + h * HDd;
    uint32_t sb = s2u(SM);

    stageA(SM, Ab, tid, mt);
    int wr = warp * 16, g = lane >> 2, t = lane & 3;

    float acc2[8][4];
    #pragma unroll
    for (int n = 0; n < 8; n++)
        #pragma unroll
        for (int j = 0; j < 4; j++) acc2[n][j] = 0.f;

    for (int ch = 0; ch < 4; ch++) {
        int j0 = ch * 64;
        __syncthreads();
        stageB(SM, Bp, tid, j0);
        __syncthreads();
        float acc1[8][4];
        mma1(sb, wr, lane, SCALE, acc1);

        __syncthreads();                 // all warps done reading SB (Q2)
        stageB(SM, Vb, tid, j0);         // restage SB with V chunk
        __syncthreads();

        #pragma unroll
        for (int ks = 0; ks < 4; ks++) {
            uint32_t sh[4], sl[4];
            sh[0] = pk2(acc1[2*ks][0],   acc1[2*ks][1]);
            sh[1] = pk2(acc1[2*ks][2],   acc1[2*ks][3]);
            sh[2] = pk2(acc1[2*ks+1][0], acc1[2*ks+1][1]);
            sh[3] = pk2(acc1[2*ks+1][2], acc1[2*ks+1][3]);
            sl[0] = pk2(lo1(acc1[2*ks][0]),   lo1(acc1[2*ks][1]));
            sl[1] = pk2(lo1(acc1[2*ks][2]),   lo1(acc1[2*ks][3]));
            sl[2] = pk2(lo1(acc1[2*ks+1][0]), lo1(acc1[2*ks+1][1]));
            sl[3] = pk2(lo1(acc1[2*ks+1][2]), lo1(acc1[2*ks+1][3]));
            #pragma unroll
            for (int n = 0; n < 8; n++) {
                int vrow = ks*16 + (lane & 15);
                int vcolb = n*16;
                uint32_t vh[2], vl[2];
                LDSM_X2T(vh, sb + SB_H + SWZ(vrow*128 + vcolb));
                LDSM_X2T(vl, sb + SB_L + SWZ(vrow*128 + vcolb));
                MMA_BF16(acc2[n], sh, vh);
                MMA_BF16(acc2[n], sh, vl);
                MMA_BF16(acc2[n], sl, vh);
            }
        }
    }

    int row0 = mt*128 + wr + g;
    float* rb = out + (size_t)batch * RV_SZ;
    #pragma unroll
    for (int n = 0; n < 8; n++) {
        int d = n*8 + 2*t;
        if (row0 < Nn)
            *(float2*)(rb + (size_t)row0 * HDd + d) =
                make_float2(acc2[n][0], acc2[n][1]);
        if (row0 + 8 < Nn)
            *(float2*)(rb + (size_t)(row0+8) * HDd + d) =
                make_float2(acc2[n][2], acc2[n][3]);
    }
}

// ----------------------------------------------------------------------------
// HMMA combine: of_z[b,h,i,d] = sum_{c in z-group} w[b,h,c]*(L_c @ RV_c)[i,d]
// ----------------------------------------------------------------------------
__global__ __launch_bounds__(256, 2) void combine_mma(
    const float* __restrict__ left, const float* __restrict__ w,
    const float* __restrict__ rv, float* __restrict__ of0, float* __restrict__ of1)
{
    __shared__ __align__(16) unsigned char SM[49152];
    int tid = threadIdx.x, lane = tid & 31, warp = tid >> 5;
    int mt = blockIdx.x;
    int bh = blockIdx.y;
    int b = bh >> 3, h = bh & 7;
    int z = blockIdx.z;
    float* ofull = z ? of1 : of0;
    uint32_t sb = s2u(SM);
    int wr = warp * 16, g = lane >> 2, t = lane & 3;

    float acc[8][4];
    #pragma unroll
    for (int n = 0; n < 8; n++)
        #pragma unroll
        for (int j = 0; j < 4; j++) acc[n][j] = 0.f;

    for (int cc = 0; cc < 5; cc++) {
        int c = z * 5 + cc;
        float wc = w[(b * Hh + h) * NCc + c];
        int batch = (b * NCc + c) * Hh + h;
        const float* Lb = left + (size_t)batch * ATT_SZ;
        const float* Rb = rv + (size_t)batch * RV_SZ;

        for (int ch = 0; ch < 4; ch++) {
            int j0 = ch * 64;
            __syncthreads();
            // stage A = wc * L[mt*128+r][j0..j0+63]  (row stride Nn)
            {
                int r = tid >> 1, half = tid & 1;
                int gi = mt * 128 + r;
                #pragma unroll
                for (int q = 0; q < 8; q++) {
                    int col = j0 + half*32 + q*4;
                    float4 v = (gi < Nn && col < Nn)
                             ? F4(Lb + (size_t)gi * Nn + col) : f4zero();
                    v.x *= wc; v.y *= wc; v.z *= wc; v.w *= wc;
                    int off = r*128 + half*64 + q*8;
                    *(uint2*)(SM + SA_H + SWZ(off)) =
                        make_uint2(pk2(v.x, v.y), pk2(v.z, v.w));
                    *(uint2*)(SM + SA_L + SWZ(off)) =
                        make_uint2(pk2(lo1(v.x), lo1(v.y)), pk2(lo1(v.z), lo1(v.w)));
                }
            }
            // stage B = RV[j0+r][0..63]  (row stride HDd)
            {
                int r = tid >> 2, q4 = tid & 3;
                int gj = j0 + r;
                #pragma unroll
                for (int q = 0; q < 4; q++) {
                    float4 v = (gj < Nn) ? F4(Rb + (size_t)gj * HDd + q4*16 + q*4)
                                         : f4zero();
                    int off = r*128 + q4*32 + q*8;
                    *(uint2*)(SM + SB_H + SWZ(off)) =
                        make_uint2(pk2(v.x, v.y), pk2(v.z, v.w));
                    *(uint2*)(SM + SB_L + SWZ(off)) =
                        make_uint2(pk2(lo1(v.x), lo1(v.y)), pk2(lo1(v.z), lo1(v.w)));
                }
            }
            __syncthreads();
            #pragma unroll
            for (int ks = 0; ks < 4; ks++) {
                int arow = wr + (lane & 15);
                int acolb = ks*32 + ((lane >> 4) << 4);
                uint32_t ah[4], al[4];
                LDSM_X4(ah, sb + SA_H + SWZ(arow*128 + acolb));
                LDSM_X4(al, sb + SA_L + SWZ(arow*128 + acolb));
                #pragma unroll
                for (int n = 0; n < 8; n++) {
                    int vrow = ks*16 + (lane & 15);
                    int vcolb = n*16;
                    uint32_t vh[2], vl[2];
                    LDSM_X2T(vh, sb + SB_H + SWZ(vrow*128 + vcolb));
                    LDSM_X2T(vl, sb + SB_L + SWZ(vrow*128 + vcolb));
                    MMA_BF16(acc[n], ah, vh);
                    MMA_BF16(acc[n], ah, vl);
                    MMA_BF16(acc[n], al, vh);
                }
            }
        }
    }

    int row0 = mt*128 + wr + g;
    float* ob = ofull + (size_t)b * (Nn * Cc) + (size_t)h * (Nn * HDd);
    #pragma unroll
    for (int n = 0; n < 8; n++) {
        int d = n*8 + 2*t;
        if (row0 < Nn)
            *(float2*)(ob + (size_t)row0 * HDd + d) =
                make_float2(acc[n][0], acc[n][1]);
        if (row0 + 8 < Nn)
            *(float2*)(ob + (size_t)(row0+8) * HDd + d) =
                make_float2(acc[n][2], acc[n][3]);
    }
}

// ----------------------------------------------------------------------------
// HMMA GEMM: O[M,512] = (A (+A2))[M,512] @ W[512,512] (+bias).
// A rows staged hi/lo (fp32 pre-sum of A2); W k-chunks via ldmatrix.x2.trans
// (K = k rows), 8 chunks of 64. blockIdx.z selects W/O.
// grid = (mtiles, 8 col-tiles, nW), 256 threads.
// ----------------------------------------------------------------------------
__global__ __launch_bounds__(256, 2) void gemm_mma(
    const float* __restrict__ A, const float* __restrict__ A2,
    const float* __restrict__ W0, const float* __restrict__ W1, const float* __restrict__ W2,
    float* __restrict__ O0, float* __restrict__ O1, float* __restrict__ O2,
    const float* __restrict__ bias, int M)
{
    __shared__ __align__(16) unsigned char SM[49152];
    int tid = threadIdx.x, lane = tid & 31, warp = tid >> 5;
    int z = blockIdx.z;
    const float* W = (z == 0) ? W0 : (z == 1 ? W1 : W2);
    float*       O = (z == 0) ? O0 : (z == 1 ? O1 : O2);
    int mt = blockIdx.x, col0 = blockIdx.y * 64;
    uint32_t sb = s2u(SM);
    int wr = warp * 16, g = lane >> 2, t = lane & 3;

    float acc[8][4];
    #pragma unroll
    for (int n = 0; n < 8; n++)
        #pragma unroll
        for (int j = 0; j < 4; j++) acc[n][j] = 0.f;

    for (int k0 = 0; k0 < 512; k0 += 64) {
        __syncthreads();
        // stage A rows (M dim), cols k0..k0+63, optional A2 fp32 pre-sum
        {
            int r = tid >> 1, half = tid & 1;
            int gr = mt * 128 + r;
            #pragma unroll
            for (int q = 0; q < 8; q++) {
                float4 v = f4zero();
                if (gr < M) {
                    v = F4(A + (size_t)gr * 512 + k0 + half*32 + q*4);
                    if (A2) {
                        float4 v2 = F4(A2 + (size_t)gr * 512 + k0 + half*32 + q*4);
                        v.x += v2.x; v.y += v2.y; v.z += v2.z; v.w += v2.w;
                    }
                }
                int off = r*128 + half*64 + q*8;
                *(uint2*)(SM + SA_H + SWZ(off)) =
                    make_uint2(pk2(v.x, v.y), pk2(v.z, v.w));
                *(uint2*)(SM + SA_L + SWZ(off)) =
                    make_uint2(pk2(lo1(v.x), lo1(v.y)), pk2(lo1(v.z), lo1(v.w)));
            }
        }
        // stage W chunk: rows k0..k0+63 (K), cols col0..col0+63 (N)
        {
            int r = tid >> 2, q4 = tid & 3;
            #pragma unroll
            for (int q = 0; q < 4; q++) {
                float4 v = F4(W + (size_t)(k0 + r) * 512 + col0 + q4*16 + q*4);
                int off = r*128 + q4*32 + q*8;
                *(uint2*)(SM + SB_H + SWZ(off)) =
                    make_uint2(pk2(v.x, v.y), pk2(v.z, v.w));
                *(uint2*)(SM + SB_L + SWZ(off)) =
                    make_uint2(pk2(lo1(v.x), lo1(v.y)), pk2(lo1(v.z), lo1(v.w)));
            }
        }
        __syncthreads();
        #pragma unroll
        for (int ks = 0; ks < 4; ks++) {
            int arow = wr + (lane & 15);
            int acolb = ks*32 + ((lane >> 4) << 4);
            uint32_t ah[4], al[4];
            LDSM_X4(ah, sb + SA_H + SWZ(arow*128 + acolb));
            LDSM_X4(al, sb + SA_L + SWZ(arow*128 + acolb));
            #pragma unroll
            for (int n = 0; n < 8; n++) {
                int vrow = ks*16 + (lane & 15);
                int vcolb = n*16;
                uint32_t vh[2], vl[2];
                LDSM_X2T(vh, sb + SB_H + SWZ(vrow*128 + vcolb));
                LDSM_X2T(vl, sb + SB_L + SWZ(vrow*128 + vcolb));
                MMA_BF16(acc[n], ah, vh);
                MMA_BF16(acc[n], ah, vl);
                MMA_BF16(acc[n], al, vh);
            }
        }
    }

    int row0 = mt*128 + wr + g;
    #pragma unroll
    for (int n = 0; n < 8; n++) {
        int d = n*8 + 2*t;
        float2 bv = make_float2(0.f, 0.f);
        if (bias) bv = *(const float2*)(bias + col0 + d);
        if (row0 < M)
            *(float2*)(O + (size_t)row0 * 512 + col0 + d) =
                make_float2(acc[n][0] + bv.x, acc[n][1] + bv.y);
        if (row0 + 8 < M)
            *(float2*)(O + (size_t)(row0+8) * 512 + col0 + d) =
                make_float2(acc[n][2] + bv.x, acc[n][3] + bv.y);
    }
}

extern "C" void kernel_launch(void* const* d_in, const int* in_sizes, int n_in,
                              void* d_out, int out_size) {
    const float* x       = (const float*)d_in[0];
    const float* anchors = (const float*)d_in[1];
    const float* weights = (const float*)d_in[2];
    const float* Wqk     = (const float*)d_in[3];
    const float* Wqk2    = (const float*)d_in[4];
    const float* Wv      = (const float*)d_in[5];
    const float* Wproj   = (const float*)d_in[6];
    const float* bproj   = (const float*)d_in[7];

    float* out  = (float*)d_out;
    float* left = out + (size_t)Bb * Nn * Cc;

    float *xq, *xq2, *xv, *aq, *aq2, *rv, *of0, *of1;
    cudaGetSymbolAddress((void**)&xq,  g_xq);
    cudaGetSymbolAddress((void**)&xq2, g_xq2);
    cudaGetSymbolAddress((void**)&xv,  g_xv);
    cudaGetSymbolAddress((void**)&aq,  g_aq);
    cudaGetSymbolAddress((void**)&aq2, g_aq2);
    cudaGetSymbolAddress((void**)&rv,  g_rv);
    cudaGetSymbolAddress((void**)&of0, g_of0);
    cudaGetSymbolAddress((void**)&of1, g_of1);

    const int MX = Bb * Nn;    // 1568 -> 13 m-tiles
    const int MA = NCc * Nn;   // 1960 -> 16 m-tiles

    // x projections (Wqk, Wqk2, Wv) - HMMA
    gemm_mma<<<dim3(13, 8, 3), 256>>>(x, nullptr, Wqk, Wqk2, Wv,
                                      xq, xq2, xv, nullptr, MX);
    // anchor projections (Wqk, Wqk2) - HMMA
    gemm_mma<<<dim3(16, 8, 2), 256>>>(anchors, nullptr, Wqk, Wqk2, Wqk,
                                      aq, aq2, aq, nullptr, MA);
    attn_left_mma<<<dim3(2, NBATCH), 256>>>(xq, aq, left);
    attn_rv_mma<<<dim3(2, NBATCH), 256>>>(aq2, xq2, xv, rv);
    combine_mma<<<dim3(2, Bb*Hh, 2), 256>>>(left, weights, rv, of0, of1);
    // final projection: A = of0 + of1, plus bias - HMMA
    gemm_mma<<<dim3(13, 8, 1), 256>>>(of0, of1, Wproj, Wproj, Wproj,
                                      out, out, out, bproj, MX);
}

// round 16
// speedup vs baseline: 3.3370x; 1.0840x over previous
#include <cuda_runtime.h>
#include <cuda_bf16.h>
#include <cstddef>
#include <cstdint>

#define Bb 8
#define Nn 196
#define Cc 512
#define NCc 10
#define Hh 8
#define HDd 64
#define SCALE 0.125f
#define NBATCH (Bb*NCc*Hh)
#define ATT_SZ (Nn*Nn)
#define RV_SZ (Nn*HDd)

__device__ float g_xq   [Bb*Nn*Cc];
__device__ float g_xq2  [Bb*Nn*Cc];
__device__ float g_xv   [Bb*Nn*Cc];
__device__ float g_aq   [NCc*Nn*Cc];
__device__ float g_aq2  [NCc*Nn*Cc];
__device__ float g_rv   [NBATCH*RV_SZ];
__device__ float g_of0  [Bb*Nn*Cc];
__device__ float g_of1  [Bb*Nn*Cc];

#define F4(p) (*(const float4*)(p))
static __device__ __forceinline__ float4 f4zero() { return make_float4(0.f,0.f,0.f,0.f); }

static __device__ __forceinline__ uint32_t s2u(const void* p) {
    uint32_t a;
    asm("{ .reg .u64 t; cvta.to.shared.u64 t, %1; cvt.u32.u64 %0, t; }" : "=r"(a) : "l"(p));
    return a;
}
static __device__ __forceinline__ unsigned pk2(float a, float b) {
    __nv_bfloat162 t; t.x = __float2bfloat16(a); t.y = __float2bfloat16(b);
    return *reinterpret_cast<unsigned*>(&t);
}
static __device__ __forceinline__ float lo1(float x) {
    return x - __bfloat162float(__float2bfloat16(x));
}
#define SWZ(o) ((o) ^ (((o) >> 3) & 0x70))

#define LDSM_X4(r, a) \
    asm volatile("ldmatrix.sync.aligned.m8n8.x4.shared.b16 {%0,%1,%2,%3}, [%4];" \
        : "=r"((r)[0]),"=r"((r)[1]),"=r"((r)[2]),"=r"((r)[3]) : "r"(a))
#define LDSM_X2(r, a) \
    asm volatile("ldmatrix.sync.aligned.m8n8.x2.shared.b16 {%0,%1}, [%2];" \
        : "=r"((r)[0]),"=r"((r)[1]) : "r"(a))
#define LDSM_X2T(r, a) \
    asm volatile("ldmatrix.sync.aligned.m8n8.x2.trans.shared.b16 {%0,%1}, [%2];" \
        : "=r"((r)[0]),"=r"((r)[1]) : "r"(a))
#define MMA_BF16(c, a, b) \
    asm volatile("mma.sync.aligned.m16n8k16.row.col.f32.bf16.bf16.f32 " \
        "{%0,%1,%2,%3}, {%4,%5,%6,%7}, {%8,%9}, {%0,%1,%2,%3};" \
        : "+f"((c)[0]),"+f"((c)[1]),"+f"((c)[2]),"+f"((c)[3]) \
        : "r"((a)[0]),"r"((a)[1]),"r"((a)[2]),"r"((a)[3]), "r"((b)[0]),"r"((b)[1]))

// SMEM: A_hi 0..16K, A_lo 16K..32K (128 rows x 128B, SW128-swizzled)
//       B_hi 32K..40K, B_lo 40K..48K (64 rows x 128B)
#define SA_H 0
#define SA_L 16384
#define SB_H 32768
#define SB_L 40960

// Shared staging helpers -----------------------------------------------------
static __device__ __forceinline__ void stageA(unsigned char* SM, const float* Ab,
                                              int tid, int mt) {
    int r = tid >> 1, half = tid & 1;
    int gr = mt * 128 + r;
    #pragma unroll
    for (int q = 0; q < 8; q++) {
        float4 v = (gr < Nn) ? F4(Ab + (size_t)gr * Cc + half*32 + q*4) : f4zero();
        int off = r*128 + half*64 + q*8;
        *(uint2*)(SM + SA_H + SWZ(off)) = make_uint2(pk2(v.x, v.y), pk2(v.z, v.w));
        *(uint2*)(SM + SA_L + SWZ(off)) =
            make_uint2(pk2(lo1(v.x), lo1(v.y)), pk2(lo1(v.z), lo1(v.w)));
    }
}
// Split staging: gmem -> regs (prefetchable), regs -> smem (convert+store).
static __device__ __forceinline__ void ldB(const float* Bp, int tid, int j0,
                                           float4 r4[4]) {
    int r = tid >> 2, q4 = tid & 3;
    int gj = j0 + r;
    #pragma unroll
    for (int q = 0; q < 4; q++)
        r4[q] = (gj < Nn) ? F4(Bp + (size_t)gj * Cc + q4*16 + q*4) : f4zero();
}
static __device__ __forceinline__ void stB(unsigned char* SM, int tid,
                                           const float4 r4[4]) {
    int r = tid >> 2, q4 = tid & 3;
    #pragma unroll
    for (int q = 0; q < 4; q++) {
        float4 v = r4[q];
        int off = r*128 + q4*32 + q*8;
        *(uint2*)(SM + SB_H + SWZ(off)) = make_uint2(pk2(v.x, v.y), pk2(v.z, v.w));
        *(uint2*)(SM + SB_L + SWZ(off)) =
            make_uint2(pk2(lo1(v.x), lo1(v.y)), pk2(lo1(v.z), lo1(v.w)));
    }
}
// MMA1: acc1 = Ah.Bh + Ah.Bl + Al.Bh over K=64, then relu*sc.
static __device__ __forceinline__ void mma1(uint32_t sb, int wr, int lane,
                                            float sc, float acc1[8][4]) {
    #pragma unroll
    for (int n = 0; n < 8; n++)
        #pragma unroll
        for (int j = 0; j < 4; j++) acc1[n][j] = 0.f;
    #pragma unroll
    for (int ks = 0; ks < 4; ks++) {
        int arow = wr + (lane & 15);
        int acolb = ks*32 + ((lane >> 4) << 4);
        uint32_t ah[4], al[4];
        LDSM_X4(ah, sb + SA_H + SWZ(arow*128 + acolb));
        LDSM_X4(al, sb + SA_L + SWZ(arow*128 + acolb));
        #pragma unroll
        for (int n = 0; n < 8; n++) {
            int brow = n*8 + (lane & 7);
            int bcolb = ks*32 + (((lane >> 3) & 1) << 4);
            uint32_t bh[2], bl[2];
            LDSM_X2(bh, sb + SB_H + SWZ(brow*128 + bcolb));
            LDSM_X2(bl, sb + SB_L + SWZ(brow*128 + bcolb));
            MMA_BF16(acc1[n], ah, bh);
            MMA_BF16(acc1[n], ah, bl);
            MMA_BF16(acc1[n], al, bh);
        }
    }
    #pragma unroll
    for (int n = 0; n < 8; n++)
        #pragma unroll
        for (int j = 0; j < 4; j++) acc1[n][j] = fmaxf(acc1[n][j] * sc, 0.f);
}

// ----------------------------------------------------------------------------
// left_attn: out[batch][i][j] = relu(-SCALE * xq[b]_i . aq[c]_j)
// Prefetch: next B chunk loaded to regs before MMA of current chunk.
// ----------------------------------------------------------------------------
__global__ __launch_bounds__(256) void attn_left_mma(
    const float* __restrict__ Pa, const float* __restrict__ Pb,
    float* __restrict__ out)
{
    __shared__ __align__(16) unsigned char SM[49152];
    int tid = threadIdx.x, lane = tid & 31, warp = tid >> 5;
    int mt = blockIdx.x, batch = blockIdx.y;
    int h = batch & 7, c = (batch >> 3) % 10, b = batch / 80;
    const float* Ab = Pa + (size_t)b * Nn * Cc + h * HDd;
    const float* Bp = Pb + (size_t)c * Nn * Cc + h * HDd;
    uint32_t sb = s2u(SM);

    float4 bReg[4];
    ldB(Bp, tid, 0, bReg);
    stageA(SM, Ab, tid, mt);
    int wr = warp * 16, g = lane >> 2, t = lane & 3;

    for (int ch = 0; ch < 4; ch++) {
        int j0 = ch * 64;
        __syncthreads();
        stB(SM, tid, bReg);
        if (ch < 3) ldB(Bp, tid, j0 + 64, bReg);   // overlaps MMA below
        __syncthreads();
        float acc1[8][4];
        mma1(sb, wr, lane, -SCALE, acc1);
        int row0 = mt*128 + wr + g;
        float* ob = out + (size_t)batch * ATT_SZ;
        #pragma unroll
        for (int n = 0; n < 8; n++) {
            int col = j0 + n*8 + 2*t;
            if (col < Nn) {
                if (row0 < Nn)
                    *(float2*)(ob + (size_t)row0 * Nn + col) =
                        make_float2(acc1[n][0], acc1[n][1]);
                if (row0 + 8 < Nn)
                    *(float2*)(ob + (size_t)(row0+8) * Nn + col) =
                        make_float2(acc1[n][2], acc1[n][3]);
            }
        }
    }
}

// ----------------------------------------------------------------------------
// fused right-attn + RV: out[batch][i][d] =
//   sum_j relu(SCALE * aq2[c]_i . xq2[b]_j) * xv[b][j][d]
// Prefetch: V chunk loaded during MMA1; next B chunk loaded during MMA2.
// ----------------------------------------------------------------------------
__global__ __launch_bounds__(256) void attn_rv_mma(
    const float* __restrict__ Pa, const float* __restrict__ Pb,
    const float* __restrict__ Vsrc, float* __restrict__ out)
{
    __shared__ __align__(16) unsigned char SM[49152];
    int tid = threadIdx.x, lane = tid & 31, warp = tid >> 5;
    int mt = blockIdx.x, batch = blockIdx.y;
    int h = batch & 7, c = (batch >> 3) % 10, b = batch / 80;
    const float* Ab = Pa + (size_t)c * Nn * Cc + h * HDd;
    const float* Bp = Pb + (size_t)b * Nn * Cc + h * HDd;
    const float* Vb = Vsrc + (size_t)b * Nn * Cc + h * HDd;
    uint32_t sb = s2u(SM);

    float4 bReg[4], vReg[4];
    ldB(Bp, tid, 0, bReg);
    stageA(SM, Ab, tid, mt);
    int wr = warp * 16, g = lane >> 2, t = lane & 3;

    float acc2[8][4];
    #pragma unroll
    for (int n = 0; n < 8; n++)
        #pragma unroll
        for (int j = 0; j < 4; j++) acc2[n][j] = 0.f;

    for (int ch = 0; ch < 4; ch++) {
        int j0 = ch * 64;
        __syncthreads();                 // prev MMA2 done with SB
        stB(SM, tid, bReg);
        ldB(Vb, tid, j0, vReg);          // V prefetch overlaps MMA1
        __syncthreads();
        float acc1[8][4];
        mma1(sb, wr, lane, SCALE, acc1);

        __syncthreads();                 // all warps done reading SB (Q2)
        stB(SM, tid, vReg);              // restage SB with V chunk
        if (ch < 3) ldB(Bp, tid, j0 + 64, bReg);   // next B overlaps MMA2
        __syncthreads();

        #pragma unroll
        for (int ks = 0; ks < 4; ks++) {
            uint32_t sh[4], sl[4];
            sh[0] = pk2(acc1[2*ks][0],   acc1[2*ks][1]);
            sh[1] = pk2(acc1[2*ks][2],   acc1[2*ks][3]);
            sh[2] = pk2(acc1[2*ks+1][0], acc1[2*ks+1][1]);
            sh[3] = pk2(acc1[2*ks+1][2], acc1[2*ks+1][3]);
            sl[0] = pk2(lo1(acc1[2*ks][0]),   lo1(acc1[2*ks][1]));
            sl[1] = pk2(lo1(acc1[2*ks][2]),   lo1(acc1[2*ks][3]));
            sl[2] = pk2(lo1(acc1[2*ks+1][0]), lo1(acc1[2*ks+1][1]));
            sl[3] = pk2(lo1(acc1[2*ks+1][2]), lo1(acc1[2*ks+1][3]));
            #pragma unroll
            for (int n = 0; n < 8; n++) {
                int vrow = ks*16 + (lane & 15);
                int vcolb = n*16;
                uint32_t vh[2], vl[2];
                LDSM_X2T(vh, sb + SB_H + SWZ(vrow*128 + vcolb));
                LDSM_X2T(vl, sb + SB_L + SWZ(vrow*128 + vcolb));
                MMA_BF16(acc2[n], sh, vh);
                MMA_BF16(acc2[n], sh, vl);
                MMA_BF16(acc2[n], sl, vh);
            }
        }
    }

    int row0 = mt*128 + wr + g;
    float* rb = out + (size_t)batch * RV_SZ;
    #pragma unroll
    for (int n = 0; n < 8; n++) {
        int d = n*8 + 2*t;
        if (row0 < Nn)
            *(float2*)(rb + (size_t)row0 * HDd + d) =
                make_float2(acc2[n][0], acc2[n][1]);
        if (row0 + 8 < Nn)
            *(float2*)(rb + (size_t)(row0+8) * HDd + d) =
                make_float2(acc2[n][2], acc2[n][3]);
    }
}

// ----------------------------------------------------------------------------
// HMMA combine: of_z[b,h,i,d] = sum_{c in z-group} w[b,h,c]*(L_c @ RV_c)[i,d]
// ----------------------------------------------------------------------------
__global__ __launch_bounds__(256) void combine_mma(
    const float* __restrict__ left, const float* __restrict__ w,
    const float* __restrict__ rv, float* __restrict__ of0, float* __restrict__ of1)
{
    __shared__ __align__(16) unsigned char SM[49152];
    int tid = threadIdx.x, lane = tid & 31, warp = tid >> 5;
    int mt = blockIdx.x;
    int bh = blockIdx.y;
    int b = bh >> 3, h = bh & 7;
    int z = blockIdx.z;
    float* ofull = z ? of1 : of0;
    uint32_t sb = s2u(SM);
    int wr = warp * 16, g = lane >> 2, t = lane & 3;

    float acc[8][4];
    #pragma unroll
    for (int n = 0; n < 8; n++)
        #pragma unroll
        for (int j = 0; j < 4; j++) acc[n][j] = 0.f;

    for (int cc = 0; cc < 5; cc++) {
        int c = z * 5 + cc;
        float wc = w[(b * Hh + h) * NCc + c];
        int batch = (b * NCc + c) * Hh + h;
        const float* Lb = left + (size_t)batch * ATT_SZ;
        const float* Rb = rv + (size_t)batch * RV_SZ;

        for (int ch = 0; ch < 4; ch++) {
            int j0 = ch * 64;
            __syncthreads();
            // stage A = wc * L[mt*128+r][j0..j0+63]  (row stride Nn)
            {
                int r = tid >> 1, half = tid & 1;
                int gi = mt * 128 + r;
                #pragma unroll
                for (int q = 0; q < 8; q++) {
                    int col = j0 + half*32 + q*4;
                    float4 v = (gi < Nn && col < Nn)
                             ? F4(Lb + (size_t)gi * Nn + col) : f4zero();
                    v.x *= wc; v.y *= wc; v.z *= wc; v.w *= wc;
                    int off = r*128 + half*64 + q*8;
                    *(uint2*)(SM + SA_H + SWZ(off)) =
                        make_uint2(pk2(v.x, v.y), pk2(v.z, v.w));
                    *(uint2*)(SM + SA_L + SWZ(off)) =
                        make_uint2(pk2(lo1(v.x), lo1(v.y)), pk2(lo1(v.z), lo1(v.w)));
                }
            }
            // stage B = RV[j0+r][0..63]  (row stride HDd)
            {
                int r = tid >> 2, q4 = tid & 3;
                int gj = j0 + r;
                #pragma unroll
                for (int q = 0; q < 4; q++) {
                    float4 v = (gj < Nn) ? F4(Rb + (size_t)gj * HDd + q4*16 + q*4)
                                         : f4zero();
                    int off = r*128 + q4*32 + q*8;
                    *(uint2*)(SM + SB_H + SWZ(off)) =
                        make_uint2(pk2(v.x, v.y), pk2(v.z, v.w));
                    *(uint2*)(SM + SB_L + SWZ(off)) =
                        make_uint2(pk2(lo1(v.x), lo1(v.y)), pk2(lo1(v.z), lo1(v.w)));
                }
            }
            __syncthreads();
            #pragma unroll
            for (int ks = 0; ks < 4; ks++) {
                int arow = wr + (lane & 15);
                int acolb = ks*32 + ((lane >> 4) << 4);
                uint32_t ah[4], al[4];
                LDSM_X4(ah, sb + SA_H + SWZ(arow*128 + acolb));
                LDSM_X4(al, sb + SA_L + SWZ(arow*128 + acolb));
                #pragma unroll
                for (int n = 0; n < 8; n++) {
                    int vrow = ks*16 + (lane & 15);
                    int vcolb = n*16;
                    uint32_t vh[2], vl[2];
                    LDSM_X2T(vh, sb + SB_H + SWZ(vrow*128 + vcolb));
                    LDSM_X2T(vl, sb + SB_L + SWZ(vrow*128 + vcolb));
                    MMA_BF16(acc[n], ah, vh);
                    MMA_BF16(acc[n], ah, vl);
                    MMA_BF16(acc[n], al, vh);
                }
            }
        }
    }

    int row0 = mt*128 + wr + g;
    float* ob = ofull + (size_t)b * (Nn * Cc) + (size_t)h * (Nn * HDd);
    #pragma unroll
    for (int n = 0; n < 8; n++) {
        int d = n*8 + 2*t;
        if (row0 < Nn)
            *(float2*)(ob + (size_t)row0 * HDd + d) =
                make_float2(acc[n][0], acc[n][1]);
        if (row0 + 8 < Nn)
            *(float2*)(ob + (size_t)(row0+8) * HDd + d) =
                make_float2(acc[n][2], acc[n][3]);
    }
}

// ----------------------------------------------------------------------------
// HMMA GEMM: O[M,512] = (A (+A2))[M,512] @ W[512,512] (+bias).
// (unchanged from round 15 - it landed with (256,2))
// ----------------------------------------------------------------------------
__global__ __launch_bounds__(256, 2) void gemm_mma(
    const float* __restrict__ A, const float* __restrict__ A2,
    const float* __restrict__ W0, const float* __restrict__ W1, const float* __restrict__ W2,
    float* __restrict__ O0, float* __restrict__ O1, float* __restrict__ O2,
    const float* __restrict__ bias, int M)
{
    __shared__ __align__(16) unsigned char SM[49152];
    int tid = threadIdx.x, lane = tid & 31, warp = tid >> 5;
    int z = blockIdx.z;
    const float* W = (z == 0) ? W0 : (z == 1 ? W1 : W2);
    float*       O = (z == 0) ? O0 : (z == 1 ? O1 : O2);
    int mt = blockIdx.x, col0 = blockIdx.y * 64;
    uint32_t sb = s2u(SM);
    int wr = warp * 16, g = lane >> 2, t = lane & 3;

    float acc[8][4];
    #pragma unroll
    for (int n = 0; n < 8; n++)
        #pragma unroll
        for (int j = 0; j < 4; j++) acc[n][j] = 0.f;

    for (int k0 = 0; k0 < 512; k0 += 64) {
        __syncthreads();
        // stage A rows (M dim), cols k0..k0+63, optional A2 fp32 pre-sum
        {
            int r = tid >> 1, half = tid & 1;
            int gr = mt * 128 + r;
            #pragma unroll
            for (int q = 0; q < 8; q++) {
                float4 v = f4zero();
                if (gr < M) {
                    v = F4(A + (size_t)gr * 512 + k0 + half*32 + q*4);
                    if (A2) {
                        float4 v2 = F4(A2 + (size_t)gr * 512 + k0 + half*32 + q*4);
                        v.x += v2.x; v.y += v2.y; v.z += v2.z; v.w += v2.w;
                    }
                }
                int off = r*128 + half*64 + q*8;
                *(uint2*)(SM + SA_H + SWZ(off)) =
                    make_uint2(pk2(v.x, v.y), pk2(v.z, v.w));
                *(uint2*)(SM + SA_L + SWZ(off)) =
                    make_uint2(pk2(lo1(v.x), lo1(v.y)), pk2(lo1(v.z), lo1(v.w)));
            }
        }
        // stage W chunk: rows k0..k0+63 (K), cols col0..col0+63 (N)
        {
            int r = tid >> 2, q4 = tid & 3;
            #pragma unroll
            for (int q = 0; q < 4; q++) {
                float4 v = F4(W + (size_t)(k0 + r) * 512 + col0 + q4*16 + q*4);
                int off = r*128 + q4*32 + q*8;
                *(uint2*)(SM + SB_H + SWZ(off)) =
                    make_uint2(pk2(v.x, v.y), pk2(v.z, v.w));
                *(uint2*)(SM + SB_L + SWZ(off)) =
                    make_uint2(pk2(lo1(v.x), lo1(v.y)), pk2(lo1(v.z), lo1(v.w)));
            }
        }
        __syncthreads();
        #pragma unroll
        for (int ks = 0; ks < 4; ks++) {
            int arow = wr + (lane & 15);
            int acolb = ks*32 + ((lane >> 4) << 4);
            uint32_t ah[4], al[4];
            LDSM_X4(ah, sb + SA_H + SWZ(arow*128 + acolb));
            LDSM_X4(al, sb + SA_L + SWZ(arow*128 + acolb));
            #pragma unroll
            for (int n = 0; n < 8; n++) {
                int vrow = ks*16 + (lane & 15);
                int vcolb = n*16;
                uint32_t vh[2], vl[2];
                LDSM_X2T(vh, sb + SB_H + SWZ(vrow*128 + vcolb));
                LDSM_X2T(vl, sb + SB_L + SWZ(vrow*128 + vcolb));
                MMA_BF16(acc[n], ah, vh);
                MMA_BF16(acc[n], ah, vl);
                MMA_BF16(acc[n], al, vh);
            }
        }
    }

    int row0 = mt*128 + wr + g;
    #pragma unroll
    for (int n = 0; n < 8; n++) {
        int d = n*8 + 2*t;
        float2 bv = make_float2(0.f, 0.f);
        if (bias) bv = *(const float2*)(bias + col0 + d);
        if (row0 < M)
            *(float2*)(O + (size_t)row0 * 512 + col0 + d) =
                make_float2(acc[n][0] + bv.x, acc[n][1] + bv.y);
        if (row0 + 8 < M)
            *(float2*)(O + (size_t)(row0+8) * 512 + col0 + d) =
                make_float2(acc[n][2] + bv.x, acc[n][3] + bv.y);
    }
}

extern "C" void kernel_launch(void* const* d_in, const int* in_sizes, int n_in,
                              void* d_out, int out_size) {
    const float* x       = (const float*)d_in[0];
    const float* anchors = (const float*)d_in[1];
    const float* weights = (const float*)d_in[2];
    const float* Wqk     = (const float*)d_in[3];
    const float* Wqk2    = (const float*)d_in[4];
    const float* Wv      = (const float*)d_in[5];
    const float* Wproj   = (const float*)d_in[6];
    const float* bproj   = (const float*)d_in[7];

    float* out  = (float*)d_out;
    float* left = out + (size_t)Bb * Nn * Cc;

    float *xq, *xq2, *xv, *aq, *aq2, *rv, *of0, *of1;
    cudaGetSymbolAddress((void**)&xq,  g_xq);
    cudaGetSymbolAddress((void**)&xq2, g_xq2);
    cudaGetSymbolAddress((void**)&xv,  g_xv);
    cudaGetSymbolAddress((void**)&aq,  g_aq);
    cudaGetSymbolAddress((void**)&aq2, g_aq2);
    cudaGetSymbolAddress((void**)&rv,  g_rv);
    cudaGetSymbolAddress((void**)&of0, g_of0);
    cudaGetSymbolAddress((void**)&of1, g_of1);

    const int MX = Bb * Nn;    // 1568 -> 13 m-tiles
    const int MA = NCc * Nn;   // 1960 -> 16 m-tiles

    // x projections (Wqk, Wqk2, Wv) - HMMA
    gemm_mma<<<dim3(13, 8, 3), 256>>>(x, nullptr, Wqk, Wqk2, Wv,
                                      xq, xq2, xv, nullptr, MX);
    // anchor projections (Wqk, Wqk2) - HMMA
    gemm_mma<<<dim3(16, 8, 2), 256>>>(anchors, nullptr, Wqk, Wqk2, Wqk,
                                      aq, aq2, aq, nullptr, MA);
    attn_left_mma<<<dim3(2, NBATCH), 256>>>(xq, aq, left);
    attn_rv_mma<<<dim3(2, NBATCH), 256>>>(aq2, xq2, xv, rv);
    combine_mma<<<dim3(2, Bb*Hh, 2), 256>>>(left, weights, rv, of0, of1);
    // final projection: A = of0 + of1, plus bias - HMMA
    gemm_mma<<<dim3(13, 8, 1), 256>>>(of0, of1, Wproj, Wproj, Wproj,
                                      out, out, out, bproj, MX);
}